// round 1
// baseline (speedup 1.0000x reference)
#include <cuda_runtime.h>
#include <cstddef>

#define NN 65536
#define EE 262144
#define GG 2048
#define DIN 9
#define HH 300
#define H2 600
#define FF 32
#define LL 5
#define DGD 1523

// ---------------- scratch (device globals; no allocation allowed) ----------
static __device__ float g_h[(size_t)NN * HH];
static __device__ float g_hv[(size_t)NN * HH];
static __device__ float g_zin[(size_t)NN * HH];
static __device__ float g_t1[(size_t)NN * H2];
static __device__ float g_z2[(size_t)NN * HH];
static __device__ float g_vn[(size_t)GG * HH];
static __device__ float g_vt[(size_t)GG * HH];
static __device__ float g_vh[(size_t)GG * H2];
static __device__ float g_stats[2 * HH];
static __device__ int   g_cnt[GG];
static __device__ float g_pool[(size_t)GG * HH];
static __device__ float g_hrep[(size_t)GG * DGD];
static __device__ float g_ph[(size_t)GG * H2];

#define GSTRIDE(i, n) for (long long i = blockIdx.x * (long long)blockDim.x + threadIdx.x; \
                           i < (long long)(n); i += (long long)gridDim.x * blockDim.x)

__global__ void k_zero_f(float* p, long long n) { GSTRIDE(i, n) p[i] = 0.f; }
__global__ void k_zero_i(int* p, long long n)   { GSTRIDE(i, n) p[i] = 0; }

// h = x @ W_emb + b_emb
__global__ void k_embed(const float* __restrict__ x, const float* __restrict__ W,
                        const float* __restrict__ b) {
    GSTRIDE(idx, (long long)NN * HH) {
        int i = (int)(idx / HH), j = (int)(idx % HH);
        float acc = b[j];
        #pragma unroll
        for (int k = 0; k < DIN; k++) acc += x[i * DIN + k] * W[k * HH + j];
        g_h[idx] = acc;
    }
}

__global__ void k_initvn(const float* __restrict__ vn0) {
    GSTRIDE(idx, (long long)GG * HH) g_vn[idx] = vn0[idx % HH];
}

// hv = h + vn[batch]; zin = (1+eps[l]) * hv
__global__ void k_hv_zinit(const int* __restrict__ batch, const float* __restrict__ eps, int l) {
    float e1 = 1.f + eps[l];
    GSTRIDE(idx, (long long)NN * HH) {
        int i = (int)(idx / HH), j = (int)(idx % HH);
        float v = g_h[idx] + g_vn[(size_t)batch[i] * HH + j];
        g_hv[idx] = v;
        g_zin[idx] = e1 * v;
    }
}

// zin[dst] += hv[src]  (neighbor-sum scatter)
__global__ void k_edge(const int* __restrict__ src, const int* __restrict__ dst) {
    GSTRIDE(idx, (long long)EE * HH) {
        int e = (int)(idx / HH), j = (int)(idx % HH);
        atomicAdd(&g_zin[(size_t)dst[e] * HH + j], g_hv[(size_t)src[e] * HH + j]);
    }
}

// ----------------- tiled SGEMM: C = epi(A[M,K] @ B[K,Nc] + bias) ------------
// MODE 0: store; 1: relu+store; 2: C += relu(v)
template <int MODE>
__global__ __launch_bounds__(256)
void k_gemm(const float* __restrict__ A, const float* __restrict__ B,
            const float* __restrict__ bias, float* __restrict__ C,
            int M, int K, int Nc) {
    __shared__ float As[16][65];
    __shared__ float Bs[16][64];
    const int tid = threadIdx.x;
    const int tx = tid & 15, ty = tid >> 4;
    const int bm = blockIdx.y * 64, bn = blockIdx.x * 64;
    float acc[4][4];
    #pragma unroll
    for (int i = 0; i < 4; i++)
        #pragma unroll
        for (int j = 0; j < 4; j++) acc[i][j] = 0.f;

    for (int k0 = 0; k0 < K; k0 += 16) {
        #pragma unroll
        for (int t = 0; t < 4; t++) {
            int q = tid + t * 256;
            int ar = q >> 4, ac = q & 15;
            float va = 0.f;
            if (bm + ar < M && k0 + ac < K) va = A[(size_t)(bm + ar) * K + k0 + ac];
            As[ac][ar] = va;
            int br = q >> 6, bc = q & 63;
            float vb = 0.f;
            if (k0 + br < K && bn + bc < Nc) vb = B[(size_t)(k0 + br) * Nc + bn + bc];
            Bs[br][bc] = vb;
        }
        __syncthreads();
        #pragma unroll
        for (int k = 0; k < 16; k++) {
            float rA[4], rB[4];
            #pragma unroll
            for (int i = 0; i < 4; i++) rA[i] = As[k][ty * 4 + i];
            #pragma unroll
            for (int j = 0; j < 4; j++) rB[j] = Bs[k][tx * 4 + j];
            #pragma unroll
            for (int i = 0; i < 4; i++)
                #pragma unroll
                for (int j = 0; j < 4; j++) acc[i][j] += rA[i] * rB[j];
        }
        __syncthreads();
    }
    #pragma unroll
    for (int i = 0; i < 4; i++) {
        int row = bm + ty * 4 + i;
        if (row >= M) continue;
        #pragma unroll
        for (int j = 0; j < 4; j++) {
            int col = bn + tx * 4 + j;
            if (col >= Nc) continue;
            float v = acc[i][j] + bias[col];
            if (MODE == 1) v = fmaxf(v, 0.f);
            if (MODE == 2) C[(size_t)row * Nc + col] += fmaxf(v, 0.f);
            else           C[(size_t)row * Nc + col] = v;
        }
    }
}

// BN statistics of g_z2: g_stats[j] += sum, g_stats[HH+j] += sumsq
__global__ __launch_bounds__(256)
void k_bnstats() {
    __shared__ float s[2 * HH];
    for (int i = threadIdx.x; i < 2 * HH; i += blockDim.x) s[i] = 0.f;
    __syncthreads();
    const int RPB = 64;
    long long base = (long long)blockIdx.x * RPB * HH;
    for (int q = threadIdx.x; q < RPB * HH; q += blockDim.x) {
        int j = q % HH;
        float v = g_z2[base + q];
        atomicAdd(&s[j], v);
        atomicAdd(&s[HH + j], v * v);
    }
    __syncthreads();
    for (int i = threadIdx.x; i < 2 * HH; i += blockDim.x) atomicAdd(&g_stats[i], s[i]);
}

// h += (optional relu of) BN(z2)
__global__ void k_bnapply(const float* __restrict__ scale, const float* __restrict__ bias,
                          int dorelu) {
    const float invN = 1.f / (float)NN;
    GSTRIDE(idx, (long long)NN * HH) {
        int j = (int)(idx % HH);
        float m = g_stats[j] * invN;
        float var = g_stats[HH + j] * invN - m * m;
        float inv = rsqrtf(var + 1e-5f);
        float z = (g_z2[idx] - m) * inv * scale[j] + bias[j];
        if (dorelu) z = fmaxf(z, 0.f);
        g_h[idx] += z;
    }
}

__global__ void k_vtinit() { GSTRIDE(idx, (long long)GG * HH) g_vt[idx] = g_vn[idx]; }

__global__ void k_vtscatter(const int* __restrict__ batch) {
    GSTRIDE(idx, (long long)NN * HH) {
        int i = (int)(idx / HH), j = (int)(idx % HH);
        atomicAdd(&g_vt[(size_t)batch[i] * HH + j], g_hv[idx]);
    }
}

__global__ void k_count(const int* __restrict__ batch) {
    GSTRIDE(i, NN) atomicAdd(&g_cnt[batch[i]], 1);
}

__global__ void k_poolscatter(const int* __restrict__ batch) {
    GSTRIDE(idx, (long long)NN * HH) {
        int i = (int)(idx / HH), j = (int)(idx % HH);
        atomicAdd(&g_pool[(size_t)batch[i] * HH + j], g_h[idx]);
    }
}

// h_rep = [pooled_h | id_pool(analytic) | morgan | maccs]
__global__ void k_assemble(const float* __restrict__ morgan, const float* __restrict__ maccs) {
    GSTRIDE(idx, (long long)GG * DGD) {
        int g = (int)(idx / DGD), c = (int)(idx % DGD);
        int cnt = g_cnt[g];
        float denom = fmaxf((float)cnt, 1.f);
        float v;
        if (c < HH) {
            v = g_pool[(size_t)g * HH + c] / denom;
        } else if (c < HH + FF) {
            int f = c - HH;
            int cf = (f < cnt) ? ((cnt - 1 - f) / FF + 1) : 0;
            v = (float)cf / denom;
        } else if (c < HH + FF + 1024) {
            v = morgan[(size_t)g * 1024 + (c - HH - FF)];
        } else {
            v = maccs[(size_t)g * 167 + (c - HH - FF - 1024)];
        }
        g_hrep[idx] = v;
    }
}

// out[g] = dot(ph[g,:], Wp2) + bp2   (TASK = 1)
__global__ __launch_bounds__(256)
void k_final(const float* __restrict__ Wp2, const float* __restrict__ bp2,
             float* __restrict__ out) {
    int g = blockIdx.x;
    float acc = 0.f;
    for (int k = threadIdx.x; k < H2; k += blockDim.x)
        acc += g_ph[(size_t)g * H2 + k] * Wp2[k];
    __shared__ float sm[256];
    sm[threadIdx.x] = acc;
    __syncthreads();
    for (int s = 128; s > 0; s >>= 1) {
        if (threadIdx.x < s) sm[threadIdx.x] += sm[threadIdx.x + s];
        __syncthreads();
    }
    if (threadIdx.x == 0) out[g] = sm[0] + bp2[0];
}

// ---------------------------------------------------------------------------
static inline int nblk(long long work, int t) {
    long long b = (work + t - 1) / t;
    return (int)b;
}

extern "C" void kernel_launch(void* const* d_in, const int* in_sizes, int n_in,
                              void* d_out, int out_size) {
    // Identify inputs by size; edge_index (2*E) and batch (N) are unique sizes,
    // everything else keeps its relative order (same in dict and signature order).
    const void* ord[21];
    int p = 0;
    const int* edge = nullptr;
    const int* batch = nullptr;
    for (int i = 0; i < n_in; i++) {
        if (in_sizes[i] == 2 * EE) edge = (const int*)d_in[i];
        else if (in_sizes[i] == NN) batch = (const int*)d_in[i];
        else if (p < 21) ord[p++] = d_in[i];
    }
    const float* x        = (const float*)ord[0];
    const float* morgan   = (const float*)ord[1];
    const float* maccs    = (const float*)ord[2];
    const float* W_emb    = (const float*)ord[3];
    const float* b_emb    = (const float*)ord[4];
    const float* gin_W1   = (const float*)ord[5];
    const float* gin_b1   = (const float*)ord[6];
    const float* gin_W2   = (const float*)ord[7];
    const float* gin_b2   = (const float*)ord[8];
    const float* bn_scale = (const float*)ord[9];
    const float* bn_bias  = (const float*)ord[10];
    const float* eps      = (const float*)ord[11];
    const float* vn0      = (const float*)ord[12];
    const float* vn_W1    = (const float*)ord[13];
    const float* vn_b1    = (const float*)ord[14];
    const float* vn_W2    = (const float*)ord[15];
    const float* vn_W2b   = (const float*)ord[16];  // vn_b2
    const float* Wp1      = (const float*)ord[17];
    const float* bp1      = (const float*)ord[18];
    const float* Wp2      = (const float*)ord[19];
    const float* bp2      = (const float*)ord[20];
    const int* src = edge;
    const int* dst = edge + EE;
    float* out = (float*)d_out;

    float *pzin, *pt1, *pz2, *pvt, *pvh, *pvn, *pstats, *ppool, *phrep, *pph;
    int* pcnt;
    cudaGetSymbolAddress((void**)&pzin, g_zin);
    cudaGetSymbolAddress((void**)&pt1, g_t1);
    cudaGetSymbolAddress((void**)&pz2, g_z2);
    cudaGetSymbolAddress((void**)&pvt, g_vt);
    cudaGetSymbolAddress((void**)&pvh, g_vh);
    cudaGetSymbolAddress((void**)&pvn, g_vn);
    cudaGetSymbolAddress((void**)&pstats, g_stats);
    cudaGetSymbolAddress((void**)&ppool, g_pool);
    cudaGetSymbolAddress((void**)&phrep, g_hrep);
    cudaGetSymbolAddress((void**)&pph, g_ph);
    cudaGetSymbolAddress((void**)&pcnt, g_cnt);

    const int T = 256;
    const long long NH = (long long)NN * HH;

    k_embed<<<nblk(NH, T), T>>>(x, W_emb, b_emb);
    k_initvn<<<nblk((long long)GG * HH, T), T>>>(vn0);

    for (int l = 0; l < LL; l++) {
        k_hv_zinit<<<nblk(NH, T), T>>>(batch, eps, l);
        k_edge<<<nblk((long long)EE * HH, T), T>>>(src, dst);

        // t1 = relu(zin @ W1 + b1) ; z2 = t1 @ W2 + b2
        {
            dim3 g1((H2 + 63) / 64, (NN + 63) / 64);
            k_gemm<1><<<g1, 256>>>(pzin, gin_W1 + (size_t)l * HH * H2,
                                   gin_b1 + (size_t)l * H2, pt1, NN, HH, H2);
            dim3 g2((HH + 63) / 64, (NN + 63) / 64);
            k_gemm<0><<<g2, 256>>>(pt1, gin_W2 + (size_t)l * H2 * HH,
                                   gin_b2 + (size_t)l * HH, pz2, NN, H2, HH);
        }

        k_zero_f<<<nblk(2 * HH, T), T>>>(pstats, 2 * HH);
        k_bnstats<<<NN / 64, 256>>>();
        k_bnapply<<<nblk(NH, T), T>>>(bn_scale + (size_t)l * HH,
                                      bn_bias + (size_t)l * HH, l < LL - 1 ? 1 : 0);

        if (l < LL - 1) {
            k_vtinit<<<nblk((long long)GG * HH, T), T>>>();
            k_vtscatter<<<nblk(NH, T), T>>>(batch);
            dim3 g1((H2 + 63) / 64, (GG + 63) / 64);
            k_gemm<1><<<g1, 256>>>(pvt, vn_W1 + (size_t)l * HH * H2,
                                   vn_b1 + (size_t)l * H2, pvh, GG, HH, H2);
            dim3 g2((HH + 63) / 64, (GG + 63) / 64);
            k_gemm<2><<<g2, 256>>>(pvh, vn_W2 + (size_t)l * H2 * HH,
                                   vn_W2b + (size_t)l * HH, pvn, GG, H2, HH);
        }
    }

    k_zero_f<<<nblk((long long)GG * HH, T), T>>>(ppool, (long long)GG * HH);
    k_zero_i<<<nblk(GG, T), T>>>(pcnt, GG);
    k_count<<<nblk(NN, T), T>>>(batch);
    k_poolscatter<<<nblk(NH, T), T>>>(batch);
    k_assemble<<<nblk((long long)GG * DGD, T), T>>>(morgan, maccs);

    {
        dim3 g1((H2 + 63) / 64, (GG + 63) / 64);
        k_gemm<1><<<g1, 256>>>(phrep, Wp1, bp1, pph, GG, DGD, H2);
    }
    k_final<<<GG, 256>>>(Wp2, bp2, out);
}

// round 2
// speedup vs baseline: 1.5083x; 1.5083x over previous
#include <cuda_runtime.h>
#include <cuda_bf16.h>
#include <cstdint>
#include <cstddef>

#define NN 65536
#define EE 262144
#define GG 2048
#define DIN 9
#define HH 300
#define H2 600
#define FF 32
#define LL 5
#define DGD 1523

// ---------------- scratch (device globals; no allocation allowed) ----------
static __device__ float g_h[(size_t)NN * HH];
static __device__ float g_hv[(size_t)NN * HH];
static __device__ float g_zin[(size_t)NN * HH];
static __device__ float g_z2[(size_t)NN * HH];
static __device__ float g_vn[(size_t)GG * HH];
static __device__ float g_vt[(size_t)GG * HH];
static __device__ float g_vh[(size_t)GG * H2];
static __device__ float g_stats[2 * HH];
static __device__ int   g_cnt[GG];
static __device__ float g_pool[(size_t)GG * HH];
static __device__ float g_hrep[(size_t)GG * DGD];
static __device__ float g_ph[(size_t)GG * H2];

// bf16 split buffers
static __device__ __nv_bfloat16 g_zin_hi[(size_t)NN * HH];
static __device__ __nv_bfloat16 g_zin_lo[(size_t)NN * HH];
static __device__ __nv_bfloat16 g_t1_hi[(size_t)NN * H2];
static __device__ __nv_bfloat16 g_t1_lo[(size_t)NN * H2];
// transposed split weights [N][K]
static __device__ __nv_bfloat16 g_W1t_hi[(size_t)H2 * HH];
static __device__ __nv_bfloat16 g_W1t_lo[(size_t)H2 * HH];
static __device__ __nv_bfloat16 g_W2t_hi[(size_t)HH * H2];
static __device__ __nv_bfloat16 g_W2t_lo[(size_t)HH * H2];

#define GSTRIDE(i, n) for (long long i = blockIdx.x * (long long)blockDim.x + threadIdx.x; \
                           i < (long long)(n); i += (long long)gridDim.x * blockDim.x)

__device__ __forceinline__ void split_bf16(float v, __nv_bfloat16& hi, __nv_bfloat16& lo) {
    hi = __float2bfloat16_rn(v);
    lo = __float2bfloat16_rn(v - __bfloat162float(hi));
}

__global__ void k_zero_f(float* p, long long n) { GSTRIDE(i, n) p[i] = 0.f; }
__global__ void k_zero_i(int* p, long long n)   { GSTRIDE(i, n) p[i] = 0; }

// h = x @ W_emb + b_emb
__global__ void k_embed(const float* __restrict__ x, const float* __restrict__ W,
                        const float* __restrict__ b) {
    GSTRIDE(idx, (long long)NN * HH) {
        int i = (int)(idx / HH), j = (int)(idx % HH);
        float acc = b[j];
        #pragma unroll
        for (int k = 0; k < DIN; k++) acc += x[i * DIN + k] * W[k * HH + j];
        g_h[idx] = acc;
    }
}

__global__ void k_initvn(const float* __restrict__ vn0) {
    GSTRIDE(idx, (long long)GG * HH) g_vn[idx] = vn0[idx % HH];
}

// hv = h + vn[batch]; zin = (1+eps[l]) * hv   (block = 4 nodes, thread = column)
__global__ void k_hv_zinit(const int* __restrict__ batch, const float* __restrict__ eps, int l) {
    int j = threadIdx.x;
    if (j >= HH) return;
    float e1 = 1.f + eps[l];
    #pragma unroll
    for (int r = 0; r < 4; r++) {
        int node = blockIdx.x * 4 + r;
        size_t o = (size_t)node * HH + j;
        float v = g_h[o] + g_vn[(size_t)batch[node] * HH + j];
        g_hv[o] = v;
        g_zin[o] = e1 * v;
    }
}

// zin[dst] += hv[src]  (block = edge, thread = column)
__global__ void k_edge2(const int* __restrict__ src, const int* __restrict__ dst) {
    int j = threadIdx.x;
    if (j >= HH) return;
    int e = blockIdx.x;
    int s = src[e], d = dst[e];
    atomicAdd(&g_zin[(size_t)d * HH + j], g_hv[(size_t)s * HH + j]);
}

// split zin -> bf16 hi/lo
__global__ void k_split_act() {
    GSTRIDE(idx, (long long)NN * HH) {
        __nv_bfloat16 hi, lo;
        split_bf16(g_zin[idx], hi, lo);
        g_zin_hi[idx] = hi;
        g_zin_lo[idx] = lo;
    }
}

// W [K][N] fp32 -> out [N][K] split bf16
__global__ void k_split_w(const float* __restrict__ W, __nv_bfloat16* __restrict__ oh,
                          __nv_bfloat16* __restrict__ ol, int K, int N) {
    GSTRIDE(idx, (long long)K * N) {
        int k = (int)(idx / N), n = (int)(idx % N);
        __nv_bfloat16 hi, lo;
        split_bf16(W[idx], hi, lo);
        oh[(size_t)n * K + k] = hi;
        ol[(size_t)n * K + k] = lo;
    }
}

// ---------------- tensor-core split-bf16 GEMM ------------------------------
// C[M,N] = A[M,K] @ B^T where Bt is [N][K]; A,B given as bf16 hi/lo splits.
// MODE 0: Cf = v + bias (fp32). MODE 1: relu(v + bias) -> split bf16 hi/lo out.
#define MMA_BF16(c, a, b) \
    asm volatile("mma.sync.aligned.m16n8k16.row.col.f32.bf16.bf16.f32 " \
                 "{%0,%1,%2,%3},{%4,%5,%6,%7},{%8,%9},{%0,%1,%2,%3};" \
                 : "+f"((c)[0]), "+f"((c)[1]), "+f"((c)[2]), "+f"((c)[3]) \
                 : "r"((a)[0]), "r"((a)[1]), "r"((a)[2]), "r"((a)[3]), \
                   "r"((b)[0]), "r"((b)[1]))

template <int MODE>
__global__ __launch_bounds__(256)
void k_mmagemm(const __nv_bfloat16* __restrict__ Ahi, const __nv_bfloat16* __restrict__ Alo,
               const __nv_bfloat16* __restrict__ Bhi, const __nv_bfloat16* __restrict__ Blo,
               const float* __restrict__ bias,
               float* __restrict__ Cf, __nv_bfloat16* __restrict__ Chi,
               __nv_bfloat16* __restrict__ Clo, int M, int K, int N) {
    constexpr int BM = 128, BN = 64, BK = 32;
    constexpr int AST = BK / 2 + 2;  // 18 b32 words per SMEM row
    constexpr int BST = BK / 2 + 2;
    __shared__ uint32_t sAhi[BM * AST], sAlo[BM * AST];
    __shared__ uint32_t sBhi[BN * BST], sBlo[BN * BST];

    const int tid = threadIdx.x;
    const int warp = tid >> 5, lane = tid & 31;
    const int wm = (warp & 3) * 32, wn = (warp >> 2) * 32;
    const int gid = lane >> 2, tig = lane & 3;
    const int bm = blockIdx.y * BM, bn = blockIdx.x * BN;
    const int Kw = K >> 1;

    float c[2][4][4];
    #pragma unroll
    for (int mi = 0; mi < 2; mi++)
        #pragma unroll
        for (int ni = 0; ni < 4; ni++)
            #pragma unroll
            for (int q = 0; q < 4; q++) c[mi][ni][q] = 0.f;

    for (int k0 = 0; k0 < K; k0 += BK) {
        const int kw0 = k0 >> 1;
        #pragma unroll
        for (int i = 0; i < 8; i++) {
            int idx = tid + i * 256;
            int r = idx >> 4, cw = idx & 15;
            uint32_t vh = 0, vl = 0;
            int gk = kw0 + cw;
            if (gk < Kw) {
                size_t o = (size_t)(bm + r) * Kw + gk;
                vh = ((const uint32_t*)Ahi)[o];
                vl = ((const uint32_t*)Alo)[o];
            }
            sAhi[r * AST + cw] = vh;
            sAlo[r * AST + cw] = vl;
        }
        #pragma unroll
        for (int i = 0; i < 4; i++) {
            int idx = tid + i * 256;
            int r = idx >> 4, cw = idx & 15;
            uint32_t vh = 0, vl = 0;
            int gk = kw0 + cw;
            if (gk < Kw && bn + r < N) {
                size_t o = (size_t)(bn + r) * Kw + gk;
                vh = ((const uint32_t*)Bhi)[o];
                vl = ((const uint32_t*)Blo)[o];
            }
            sBhi[r * BST + cw] = vh;
            sBlo[r * BST + cw] = vl;
        }
        __syncthreads();
        #pragma unroll
        for (int kk = 0; kk < 2; kk++) {
            const int kb = kk * 8;
            uint32_t ah[2][4], al[2][4], bh[4][2], bl[4][2];
            #pragma unroll
            for (int mi = 0; mi < 2; mi++) {
                int m = wm + mi * 16 + gid;
                int base = m * AST + kb + tig;
                int base8 = base + 8 * AST;
                ah[mi][0] = sAhi[base];      al[mi][0] = sAlo[base];
                ah[mi][1] = sAhi[base8];     al[mi][1] = sAlo[base8];
                ah[mi][2] = sAhi[base + 4];  al[mi][2] = sAlo[base + 4];
                ah[mi][3] = sAhi[base8 + 4]; al[mi][3] = sAlo[base8 + 4];
            }
            #pragma unroll
            for (int ni = 0; ni < 4; ni++) {
                int n = wn + ni * 8 + gid;
                int base = n * BST + kb + tig;
                bh[ni][0] = sBhi[base];     bl[ni][0] = sBlo[base];
                bh[ni][1] = sBhi[base + 4]; bl[ni][1] = sBlo[base + 4];
            }
            #pragma unroll
            for (int mi = 0; mi < 2; mi++)
                #pragma unroll
                for (int ni = 0; ni < 4; ni++) {
                    MMA_BF16(c[mi][ni], ah[mi], bh[ni]);
                    MMA_BF16(c[mi][ni], ah[mi], bl[ni]);
                    MMA_BF16(c[mi][ni], al[mi], bh[ni]);
                }
        }
        __syncthreads();
    }

    #pragma unroll
    for (int mi = 0; mi < 2; mi++) {
        #pragma unroll
        for (int ni = 0; ni < 4; ni++) {
            int col = bn + wn + ni * 8 + tig * 2;
            if (col >= N) continue;
            float b0 = bias[col], b1 = bias[col + 1];
            #pragma unroll
            for (int h = 0; h < 2; h++) {
                int row = bm + wm + mi * 16 + gid + h * 8;
                if (row >= M) continue;
                float v0 = c[mi][ni][h * 2 + 0] + b0;
                float v1 = c[mi][ni][h * 2 + 1] + b1;
                if (MODE == 0) {
                    Cf[(size_t)row * N + col] = v0;
                    Cf[(size_t)row * N + col + 1] = v1;
                } else {
                    v0 = fmaxf(v0, 0.f);
                    v1 = fmaxf(v1, 0.f);
                    __nv_bfloat16 h0, l0, h1, l1;
                    split_bf16(v0, h0, l0);
                    split_bf16(v1, h1, l1);
                    __nv_bfloat162 ph, pl;
                    ph.x = h0; ph.y = h1;
                    pl.x = l0; pl.y = l1;
                    size_t wo = (size_t)row * (N >> 1) + (col >> 1);
                    ((__nv_bfloat162*)Chi)[wo] = ph;
                    ((__nv_bfloat162*)Clo)[wo] = pl;
                }
            }
        }
    }
}

// ----------------- fp32 tiled SGEMM (small GEMMs: VN MLP, predictor) -------
template <int MODE>
__global__ __launch_bounds__(256)
void k_gemm(const float* __restrict__ A, const float* __restrict__ B,
            const float* __restrict__ bias, float* __restrict__ C,
            int M, int K, int Nc) {
    __shared__ float As[16][65];
    __shared__ float Bs[16][64];
    const int tid = threadIdx.x;
    const int tx = tid & 15, ty = tid >> 4;
    const int bm = blockIdx.y * 64, bn = blockIdx.x * 64;
    float acc[4][4];
    #pragma unroll
    for (int i = 0; i < 4; i++)
        #pragma unroll
        for (int j = 0; j < 4; j++) acc[i][j] = 0.f;

    for (int k0 = 0; k0 < K; k0 += 16) {
        #pragma unroll
        for (int t = 0; t < 4; t++) {
            int q = tid + t * 256;
            int ar = q >> 4, ac = q & 15;
            float va = 0.f;
            if (bm + ar < M && k0 + ac < K) va = A[(size_t)(bm + ar) * K + k0 + ac];
            As[ac][ar] = va;
            int br = q >> 6, bc = q & 63;
            float vb = 0.f;
            if (k0 + br < K && bn + bc < Nc) vb = B[(size_t)(k0 + br) * Nc + bn + bc];
            Bs[br][bc] = vb;
        }
        __syncthreads();
        #pragma unroll
        for (int k = 0; k < 16; k++) {
            float rA[4], rB[4];
            #pragma unroll
            for (int i = 0; i < 4; i++) rA[i] = As[k][ty * 4 + i];
            #pragma unroll
            for (int j = 0; j < 4; j++) rB[j] = Bs[k][tx * 4 + j];
            #pragma unroll
            for (int i = 0; i < 4; i++)
                #pragma unroll
                for (int j = 0; j < 4; j++) acc[i][j] += rA[i] * rB[j];
        }
        __syncthreads();
    }
    #pragma unroll
    for (int i = 0; i < 4; i++) {
        int row = bm + ty * 4 + i;
        if (row >= M) continue;
        #pragma unroll
        for (int j = 0; j < 4; j++) {
            int col = bn + tx * 4 + j;
            if (col >= Nc) continue;
            float v = acc[i][j] + bias[col];
            if (MODE == 1) v = fmaxf(v, 0.f);
            if (MODE == 2) C[(size_t)row * Nc + col] += fmaxf(v, 0.f);
            else           C[(size_t)row * Nc + col] = v;
        }
    }
}

// BN stats: block = 64 rows, thread = column; local accumulate, 2 global atomics
__global__ __launch_bounds__(320)
void k_bnstats() {
    int j = threadIdx.x;
    if (j >= HH) return;
    long long r0 = (long long)blockIdx.x * 64;
    float s = 0.f, ss = 0.f;
    for (int r = 0; r < 64; r++) {
        float v = g_z2[(r0 + r) * HH + j];
        s += v;
        ss += v * v;
    }
    atomicAdd(&g_stats[j], s);
    atomicAdd(&g_stats[HH + j], ss);
}

// h += (optional relu of) BN(z2)
__global__ void k_bnapply(const float* __restrict__ scale, const float* __restrict__ bias,
                          int dorelu) {
    int j = threadIdx.x;
    if (j >= HH) return;
    const float invN = 1.f / (float)NN;
    float m = g_stats[j] * invN;
    float var = g_stats[HH + j] * invN - m * m;
    float co = rsqrtf(var + 1e-5f) * scale[j];
    float bi = bias[j];
    #pragma unroll
    for (int r = 0; r < 4; r++) {
        size_t o = (size_t)(blockIdx.x * 4 + r) * HH + j;
        float z = (g_z2[o] - m) * co + bi;
        if (dorelu) z = fmaxf(z, 0.f);
        g_h[o] += z;
    }
}

__global__ void k_vtinit() { GSTRIDE(idx, (long long)GG * HH) g_vt[idx] = g_vn[idx]; }

__global__ void k_vtscatter(const int* __restrict__ batch) {
    int j = threadIdx.x;
    if (j >= HH) return;
    #pragma unroll
    for (int r = 0; r < 4; r++) {
        int node = blockIdx.x * 4 + r;
        atomicAdd(&g_vt[(size_t)batch[node] * HH + j], g_hv[(size_t)node * HH + j]);
    }
}

__global__ void k_count(const int* __restrict__ batch) {
    GSTRIDE(i, NN) atomicAdd(&g_cnt[batch[i]], 1);
}

__global__ void k_poolscatter(const int* __restrict__ batch) {
    int j = threadIdx.x;
    if (j >= HH) return;
    #pragma unroll
    for (int r = 0; r < 4; r++) {
        int node = blockIdx.x * 4 + r;
        atomicAdd(&g_pool[(size_t)batch[node] * HH + j], g_h[(size_t)node * HH + j]);
    }
}

// h_rep = [pooled_h | id_pool(analytic) | morgan | maccs]
__global__ void k_assemble(const float* __restrict__ morgan, const float* __restrict__ maccs) {
    GSTRIDE(idx, (long long)GG * DGD) {
        int g = (int)(idx / DGD), c = (int)(idx % DGD);
        int cnt = g_cnt[g];
        float denom = fmaxf((float)cnt, 1.f);
        float v;
        if (c < HH) {
            v = g_pool[(size_t)g * HH + c] / denom;
        } else if (c < HH + FF) {
            int f = c - HH;
            int cf = (f < cnt) ? ((cnt - 1 - f) / FF + 1) : 0;
            v = (float)cf / denom;
        } else if (c < HH + FF + 1024) {
            v = morgan[(size_t)g * 1024 + (c - HH - FF)];
        } else {
            v = maccs[(size_t)g * 167 + (c - HH - FF - 1024)];
        }
        g_hrep[idx] = v;
    }
}

// out[g] = dot(ph[g,:], Wp2) + bp2   (TASK = 1)
__global__ __launch_bounds__(256)
void k_final(const float* __restrict__ Wp2, const float* __restrict__ bp2,
             float* __restrict__ out) {
    int g = blockIdx.x;
    float acc = 0.f;
    for (int k = threadIdx.x; k < H2; k += blockDim.x)
        acc += g_ph[(size_t)g * H2 + k] * Wp2[k];
    __shared__ float sm[256];
    sm[threadIdx.x] = acc;
    __syncthreads();
    for (int s = 128; s > 0; s >>= 1) {
        if (threadIdx.x < s) sm[threadIdx.x] += sm[threadIdx.x + s];
        __syncthreads();
    }
    if (threadIdx.x == 0) out[g] = sm[0] + bp2[0];
}

// ---------------------------------------------------------------------------
static inline int nblk(long long work, int t) { return (int)((work + t - 1) / t); }

extern "C" void kernel_launch(void* const* d_in, const int* in_sizes, int n_in,
                              void* d_out, int out_size) {
    const void* ord[21];
    int p = 0;
    const int* edge = nullptr;
    const int* batch = nullptr;
    for (int i = 0; i < n_in; i++) {
        if (in_sizes[i] == 2 * EE) edge = (const int*)d_in[i];
        else if (in_sizes[i] == NN) batch = (const int*)d_in[i];
        else if (p < 21) ord[p++] = d_in[i];
    }
    const float* x        = (const float*)ord[0];
    const float* morgan   = (const float*)ord[1];
    const float* maccs    = (const float*)ord[2];
    const float* W_emb    = (const float*)ord[3];
    const float* b_emb    = (const float*)ord[4];
    const float* gin_W1   = (const float*)ord[5];
    const float* gin_b1   = (const float*)ord[6];
    const float* gin_W2   = (const float*)ord[7];
    const float* gin_b2   = (const float*)ord[8];
    const float* bn_scale = (const float*)ord[9];
    const float* bn_bias  = (const float*)ord[10];
    const float* eps      = (const float*)ord[11];
    const float* vn0      = (const float*)ord[12];
    const float* vn_W1    = (const float*)ord[13];
    const float* vn_b1    = (const float*)ord[14];
    const float* vn_W2    = (const float*)ord[15];
    const float* vn_b2    = (const float*)ord[16];
    const float* Wp1      = (const float*)ord[17];
    const float* bp1      = (const float*)ord[18];
    const float* Wp2      = (const float*)ord[19];
    const float* bp2      = (const float*)ord[20];
    const int* src = edge;
    const int* dst = edge + EE;
    float* out = (float*)d_out;

    float *pz2, *pvt, *pvh, *pvn, *pstats, *ppool, *phrep, *pph;
    int* pcnt;
    __nv_bfloat16 *pzh, *pzl, *pt1h, *pt1l, *pw1h, *pw1l, *pw2h, *pw2l;
    cudaGetSymbolAddress((void**)&pz2, g_z2);
    cudaGetSymbolAddress((void**)&pvt, g_vt);
    cudaGetSymbolAddress((void**)&pvh, g_vh);
    cudaGetSymbolAddress((void**)&pvn, g_vn);
    cudaGetSymbolAddress((void**)&pstats, g_stats);
    cudaGetSymbolAddress((void**)&ppool, g_pool);
    cudaGetSymbolAddress((void**)&phrep, g_hrep);
    cudaGetSymbolAddress((void**)&pph, g_ph);
    cudaGetSymbolAddress((void**)&pcnt, g_cnt);
    cudaGetSymbolAddress((void**)&pzh, g_zin_hi);
    cudaGetSymbolAddress((void**)&pzl, g_zin_lo);
    cudaGetSymbolAddress((void**)&pt1h, g_t1_hi);
    cudaGetSymbolAddress((void**)&pt1l, g_t1_lo);
    cudaGetSymbolAddress((void**)&pw1h, g_W1t_hi);
    cudaGetSymbolAddress((void**)&pw1l, g_W1t_lo);
    cudaGetSymbolAddress((void**)&pw2h, g_W2t_hi);
    cudaGetSymbolAddress((void**)&pw2l, g_W2t_lo);

    const int T = 256;
    const long long NH = (long long)NN * HH;

    k_embed<<<nblk(NH, T), T>>>(x, W_emb, b_emb);
    k_initvn<<<nblk((long long)GG * HH, T), T>>>(vn0);

    for (int l = 0; l < LL; l++) {
        k_split_w<<<nblk((long long)HH * H2, T), T>>>(gin_W1 + (size_t)l * HH * H2,
                                                      pw1h, pw1l, HH, H2);
        k_split_w<<<nblk((long long)HH * H2, T), T>>>(gin_W2 + (size_t)l * H2 * HH,
                                                      pw2h, pw2l, H2, HH);
        k_hv_zinit<<<NN / 4, 320>>>(batch, eps, l);
        k_edge2<<<EE, 320>>>(src, dst);
        k_split_act<<<nblk(NH, T), T>>>();

        {
            dim3 g1((H2 + 63) / 64, NN / 128);
            k_mmagemm<1><<<g1, 256>>>(pzh, pzl, pw1h, pw1l, gin_b1 + (size_t)l * H2,
                                      nullptr, pt1h, pt1l, NN, HH, H2);
            dim3 g2((HH + 63) / 64, NN / 128);
            k_mmagemm<0><<<g2, 256>>>(pt1h, pt1l, pw2h, pw2l, gin_b2 + (size_t)l * HH,
                                      pz2, nullptr, nullptr, NN, H2, HH);
        }

        k_zero_f<<<nblk(2 * HH, T), T>>>(pstats, 2 * HH);
        k_bnstats<<<NN / 64, 320>>>();
        k_bnapply<<<NN / 4, 320>>>(bn_scale + (size_t)l * HH,
                                   bn_bias + (size_t)l * HH, l < LL - 1 ? 1 : 0);

        if (l < LL - 1) {
            k_vtinit<<<nblk((long long)GG * HH, T), T>>>();
            k_vtscatter<<<NN / 4, 320>>>(batch);
            dim3 g1((H2 + 63) / 64, (GG + 63) / 64);
            k_gemm<1><<<g1, 256>>>(pvt, vn_W1 + (size_t)l * HH * H2,
                                   vn_b1 + (size_t)l * H2, pvh, GG, HH, H2);
            dim3 g2((HH + 63) / 64, (GG + 63) / 64);
            k_gemm<2><<<g2, 256>>>(pvh, vn_W2 + (size_t)l * H2 * HH,
                                   vn_b2 + (size_t)l * HH, pvn, GG, H2, HH);
        }
    }

    k_zero_f<<<nblk((long long)GG * HH, T), T>>>(ppool, (long long)GG * HH);
    k_zero_i<<<nblk(GG, T), T>>>(pcnt, GG);
    k_count<<<nblk(NN, T), T>>>(batch);
    k_poolscatter<<<NN / 4, 320>>>(batch);
    k_assemble<<<nblk((long long)GG * DGD, T), T>>>(morgan, maccs);

    {
        dim3 g1((H2 + 63) / 64, (GG + 63) / 64);
        k_gemm<1><<<g1, 256>>>(phrep, Wp1, bp1, pph, GG, DGD, H2);
    }
    k_final<<<GG, 256>>>(Wp2, bp2, out);
}

// round 4
// speedup vs baseline: 2.3197x; 1.5379x over previous
#include <cuda_runtime.h>
#include <cuda_bf16.h>
#include <cstdint>
#include <cstddef>

#define NN 65536
#define EE 262144
#define GG 2048
#define DIN 9
#define HH 300
#define H2 600
#define FF 32
#define LL 5
#define DGP 1524
#define KP1 320
#define KP2 608
#define KPP 1536

// ---------------- scratch (device globals; no allocation allowed) ----------
static __device__ float g_h[(size_t)NN * HH];
static __device__ float g_hv[(size_t)NN * HH];
static __device__ float g_zin[(size_t)NN * HH];
static __device__ float g_z2[(size_t)NN * HH];
static __device__ float g_vn[(size_t)GG * HH];
static __device__ float g_vt[(size_t)GG * HH];
static __device__ float g_stats[2 * HH];
static __device__ float g_pool[(size_t)GG * HH];
static __device__ float g_hrep[(size_t)GG * DGP];
static __device__ float g_ph[(size_t)GG * H2];
static __device__ int g_deg[NN];
static __device__ int g_off[NN + 1];
static __device__ int g_cur[NN];
static __device__ int g_csr[EE];
static __device__ int g_gcnt[GG];
static __device__ int g_gstart[GG];

static __device__ __align__(16) __nv_bfloat16 g_t1h[(size_t)NN * KP2];
static __device__ __align__(16) __nv_bfloat16 g_t1l[(size_t)NN * KP2];
static __device__ __align__(16) __nv_bfloat16 g_vhh[(size_t)GG * KP2];
static __device__ __align__(16) __nv_bfloat16 g_vhl[(size_t)GG * KP2];
static __device__ __align__(16) __nv_bfloat16 g_gW1h[(size_t)LL * H2 * KP1];
static __device__ __align__(16) __nv_bfloat16 g_gW1l[(size_t)LL * H2 * KP1];
static __device__ __align__(16) __nv_bfloat16 g_gW2h[(size_t)LL * HH * KP2];
static __device__ __align__(16) __nv_bfloat16 g_gW2l[(size_t)LL * HH * KP2];
static __device__ __align__(16) __nv_bfloat16 g_vW1h[(size_t)(LL - 1) * H2 * KP1];
static __device__ __align__(16) __nv_bfloat16 g_vW1l[(size_t)(LL - 1) * H2 * KP1];
static __device__ __align__(16) __nv_bfloat16 g_vW2h[(size_t)(LL - 1) * HH * KP2];
static __device__ __align__(16) __nv_bfloat16 g_vW2l[(size_t)(LL - 1) * HH * KP2];
static __device__ __align__(16) __nv_bfloat16 g_Wph[(size_t)H2 * KPP];
static __device__ __align__(16) __nv_bfloat16 g_Wpl[(size_t)H2 * KPP];

#define GSTRIDE(i, n) for (int i = blockIdx.x * blockDim.x + threadIdx.x; \
                           i < (int)(n); i += gridDim.x * blockDim.x)

__device__ __forceinline__ void split_bf16(float v, __nv_bfloat16& hi, __nv_bfloat16& lo) {
    hi = __float2bfloat16_rn(v);
    lo = __float2bfloat16_rn(v - __bfloat162float(hi));
}
__device__ __forceinline__ uint32_t pack2(__nv_bfloat16 a, __nv_bfloat16 b) {
    __nv_bfloat162 t; t.x = a; t.y = b;
    return *(uint32_t*)&t;
}
__device__ __forceinline__ uint32_t smem_u32(const void* p) {
    uint32_t a;
    asm("{ .reg .u64 t; cvta.to.shared.u64 t, %1; cvt.u32.u64 %0, t; }" : "=r"(a) : "l"(p));
    return a;
}

// ------------------------- small kernels -----------------------------------
__global__ void k_zero_f(float* p, int n) { GSTRIDE(i, n) p[i] = 0.f; }
__global__ void k_zero_i(int* p, int n)   { GSTRIDE(i, n) p[i] = 0; }

__global__ void k_embed(const float* __restrict__ x, const float* __restrict__ W,
                        const float* __restrict__ b) {
    int j = threadIdx.x;
    if (j >= HH) return;
    float bj = b[j];
    #pragma unroll
    for (int r = 0; r < 4; r++) {
        int node = blockIdx.x * 4 + r;
        const float* xr = x + (size_t)node * DIN;
        float acc = bj;
        #pragma unroll
        for (int k = 0; k < DIN; k++) acc += xr[k] * W[k * HH + j];
        g_h[(size_t)node * HH + j] = acc;
    }
}

__global__ void k_initvn(const float* __restrict__ vn0) {
    GSTRIDE(idx, GG * HH) g_vn[idx] = vn0[idx % HH];
}

// hv = h + vn[batch]
__global__ void k_hv(const int* __restrict__ batch) {
    int j = threadIdx.x;
    if (j >= HH) return;
    #pragma unroll
    for (int r = 0; r < 4; r++) {
        int node = blockIdx.x * 4 + r;
        g_hv[(size_t)node * HH + j] =
            g_h[(size_t)node * HH + j] + g_vn[(size_t)batch[node] * HH + j];
    }
}

// zin[n] = (1+eps)*hv[n] + sum_{e: dst==n} hv[src[e]]   (CSR gather, no atomics)
__global__ void k_gather(const float* __restrict__ eps, int l) {
    int j = threadIdx.x;
    if (j >= HH) return;
    int n = blockIdx.x;
    float e1 = 1.f + eps[l];
    float acc = e1 * g_hv[(size_t)n * HH + j];
    int e0 = g_off[n], e1i = g_off[n + 1];
    for (int e = e0; e < e1i; e++) {
        int s = g_csr[e];
        acc += g_hv[(size_t)s * HH + j];
    }
    g_zin[(size_t)n * HH + j] = acc;
}

// ---------------------- CSR / segment build --------------------------------
__global__ void k_histe(const int* __restrict__ dst) {
    GSTRIDE(e, EE) atomicAdd(&g_deg[dst[e]], 1);
}
__global__ void k_scatter(const int* __restrict__ src, const int* __restrict__ dst) {
    GSTRIDE(e, EE) {
        int pos = atomicAdd(&g_cur[dst[e]], 1);
        g_csr[pos] = src[e];
    }
}
__global__ void k_histg(const int* __restrict__ batch) {
    GSTRIDE(i, NN) atomicAdd(&g_gcnt[batch[i]], 1);
}
// single-block exclusive scan of g_deg[65536] -> g_off, g_cur
__global__ void __launch_bounds__(1024) k_scan_off() {
    __shared__ int sh[1024];
    int t = threadIdx.x;
    int base = t * 64;
    int s = 0;
    for (int i = 0; i < 64; i++) s += g_deg[base + i];
    sh[t] = s;
    __syncthreads();
    int mysum = s;
    for (int d = 1; d < 1024; d <<= 1) {
        int v = (t >= d) ? sh[t - d] : 0;
        __syncthreads();
        sh[t] += v;
        __syncthreads();
    }
    int off = sh[t] - mysum;
    for (int i = 0; i < 64; i++) {
        g_off[base + i] = off;
        g_cur[base + i] = off;
        off += g_deg[base + i];
    }
    if (t == 1023) g_off[NN] = off;
}
// single-block exclusive scan of g_gcnt[2048] -> g_gstart
__global__ void __launch_bounds__(1024) k_scan_g() {
    __shared__ int sh[1024];
    int t = threadIdx.x;
    int a0 = g_gcnt[2 * t], a1 = g_gcnt[2 * t + 1];
    int s = a0 + a1;
    sh[t] = s;
    __syncthreads();
    for (int d = 1; d < 1024; d <<= 1) {
        int v = (t >= d) ? sh[t - d] : 0;
        __syncthreads();
        sh[t] += v;
        __syncthreads();
    }
    int off = sh[t] - s;
    g_gstart[2 * t] = off;
    g_gstart[2 * t + 1] = off + a0;
}

// ---------------------- weight splitting -----------------------------------
// W layers: [L][K][N] fp32 -> [L][N][Kp] split bf16, zero-padded in K
__global__ void k_splitw(const float* __restrict__ W, __nv_bfloat16* __restrict__ oh,
                         __nv_bfloat16* __restrict__ ol, int K, int N, int Kp) {
    int l = blockIdx.y;
    const float* Ws = W + (size_t)l * K * N;
    __nv_bfloat16* ohs = oh + (size_t)l * N * Kp;
    __nv_bfloat16* ols = ol + (size_t)l * N * Kp;
    GSTRIDE(idx, N * Kp) {
        int n = idx / Kp, k = idx % Kp;
        float v = (k < K) ? Ws[(size_t)k * N + n] : 0.f;
        __nv_bfloat16 hi, lo;
        split_bf16(v, hi, lo);
        ohs[idx] = hi;
        ols[idx] = lo;
    }
}

// zero the K-padding columns of t1 / vh split buffers (cols 600..607)
__global__ void k_zero_pad() {
    GSTRIDE(i, NN + GG) {
        uint4 z = make_uint4(0, 0, 0, 0);
        if (i < NN) {
            *(uint4*)(g_t1h + (size_t)i * KP2 + H2) = z;
            *(uint4*)(g_t1l + (size_t)i * KP2 + H2) = z;
        } else {
            int r = i - NN;
            *(uint4*)(g_vhh + (size_t)r * KP2 + H2) = z;
            *(uint4*)(g_vhl + (size_t)r * KP2 + H2) = z;
        }
    }
}

// ---------------------- mma.sync GEMM ---------------------------------------
// C[M,N] = epi(A[M,K] @ Bt[N,K]^T + bias). 3 bf16 passes: hi*hi + hi*lo + lo*hi.
// ASPLIT=1: A fp32 (lda=K, split inline). ASPLIT=0: A pre-split bf16 (stride NC*32).
// MODE 0: fp32 store. 1: relu -> split bf16 store (ldc stride). 2: Cf += relu.
// 3: relu -> fp32 store.
#define RS_B 80
#define A_OFF 0
#define AL_OFF 10240
#define BH_OFF 20480
#define BL_OFF 30720
#define STAGE 40960
#define SMEMSZ (2 * STAGE)

#define MMA(c, a, b0v, b1v) \
    asm volatile("mma.sync.aligned.m16n8k16.row.col.f32.bf16.bf16.f32 " \
                 "{%0,%1,%2,%3},{%4,%5,%6,%7},{%8,%9},{%0,%1,%2,%3};" \
                 : "+f"((c)[0]), "+f"((c)[1]), "+f"((c)[2]), "+f"((c)[3]) \
                 : "r"((a)[0]), "r"((a)[1]), "r"((a)[2]), "r"((a)[3]), \
                   "r"(b0v), "r"(b1v))
#define CP16(dst, src) \
    asm volatile("cp.async.cg.shared.global [%0], [%1], 16;" :: "r"(dst), "l"(src))
#define CPCOMMIT asm volatile("cp.async.commit_group;" ::: "memory")
#define CPWAIT1 asm volatile("cp.async.wait_group 1;" ::: "memory")
#define CPWAIT0 asm volatile("cp.async.wait_group 0;" ::: "memory")

__device__ __forceinline__ void ldsm4(uint32_t& r0, uint32_t& r1, uint32_t& r2,
                                      uint32_t& r3, uint32_t a) {
    asm volatile("ldmatrix.sync.aligned.m8n8.x4.shared.b16 {%0,%1,%2,%3}, [%4];"
                 : "=r"(r0), "=r"(r1), "=r"(r2), "=r"(r3) : "r"(a));
}

template <int MODE, int ASPLIT>
__global__ void __launch_bounds__(256)
k_mma(const float* __restrict__ Af,
      const __nv_bfloat16* __restrict__ Ah, const __nv_bfloat16* __restrict__ Al,
      const __nv_bfloat16* __restrict__ Bh, const __nv_bfloat16* __restrict__ Bl,
      const float* __restrict__ bias, float* __restrict__ Cf,
      __nv_bfloat16* __restrict__ Ch, __nv_bfloat16* __restrict__ Cl,
      int K, int N, int ldc) {
    extern __shared__ __align__(16) char sm[];
    const uint32_t sb = smem_u32(sm);
    const int tid = threadIdx.x, wid = tid >> 5, lane = tid & 31;
    const int bm = blockIdx.y * 128, n0 = blockIdx.x * 128;
    const int NC = (K + 31) >> 5;
    const int strideH = NC << 5;  // padded half-stride for bf16 operands

    auto load_stage = [&](int c, int s) {
        char* bufc = sm + s * STAGE;
        uint32_t bufu = sb + s * STAGE;
        const int kh0 = c << 5;
        if (ASPLIT) {
            #pragma unroll
            for (int u = 0; u < 8; u++) {
                int idx = tid + (u << 8);
                int r = idx >> 4, kk = (idx & 15) << 1;
                int gk = kh0 + kk;
                float2 v = make_float2(0.f, 0.f);
                if (gk < K) v = *(const float2*)(Af + (size_t)(bm + r) * K + gk);
                __nv_bfloat16 h0, l0, h1, l1;
                split_bf16(v.x, h0, l0);
                split_bf16(v.y, h1, l1);
                uint32_t off = (uint32_t)r * RS_B + ((uint32_t)kk << 1);
                *(uint32_t*)(bufc + A_OFF + off) = pack2(h0, h1);
                *(uint32_t*)(bufc + AL_OFF + off) = pack2(l0, l1);
            }
        } else {
            #pragma unroll
            for (int u = 0; u < 2; u++) {
                int idx = tid + (u << 8);
                int r = idx >> 2, kc = idx & 3;
                uint32_t doff = (uint32_t)r * RS_B + ((uint32_t)kc << 4);
                size_t go = (size_t)(bm + r) * strideH + kh0 + (kc << 3);
                CP16(bufu + A_OFF + doff, Ah + go);
                CP16(bufu + AL_OFF + doff, Al + go);
            }
        }
        #pragma unroll
        for (int u = 0; u < 2; u++) {
            int idx = tid + (u << 8);
            int r = idx >> 2, kc = idx & 3;
            uint32_t doff = (uint32_t)r * RS_B + ((uint32_t)kc << 4);
            int gn = n0 + r;
            if (gn < N) {
                size_t go = (size_t)gn * strideH + kh0 + (kc << 3);
                CP16(bufu + BH_OFF + doff, Bh + go);
                CP16(bufu + BL_OFF + doff, Bl + go);
            } else {
                uint4 z = make_uint4(0, 0, 0, 0);
                *(uint4*)(bufc + BH_OFF + doff) = z;
                *(uint4*)(bufc + BL_OFF + doff) = z;
            }
        }
    };

    const int wm = (wid & 3) << 5, wn = (wid >> 2) << 6;
    const uint32_t aBase = (uint32_t)((wm + (lane & 15)) * RS_B + ((lane >> 4) << 4));
    const uint32_t bBase = (uint32_t)((wn + ((lane >> 4) << 3) + (lane & 7)) * RS_B +
                                      (((lane >> 3) & 1) << 4));

    float acc[2][8][4];
    #pragma unroll
    for (int a = 0; a < 2; a++)
        #pragma unroll
        for (int b = 0; b < 8; b++)
            #pragma unroll
            for (int q = 0; q < 4; q++) acc[a][b][q] = 0.f;

    load_stage(0, 0);
    CPCOMMIT;
    if (NC > 1) load_stage(1, 1);
    CPCOMMIT;

    for (int c = 0; c < NC; c++) {
        if (c == NC - 1) { CPWAIT0; } else { CPWAIT1; }
        __syncthreads();
        uint32_t st = sb + (c & 1) * STAGE;
        #pragma unroll
        for (int kb = 0; kb < 64; kb += 32) {
            uint32_t ah0[4], ah1[4], al0[4], al1[4];
            ldsm4(ah0[0], ah0[1], ah0[2], ah0[3], st + A_OFF + aBase + kb);
            ldsm4(ah1[0], ah1[1], ah1[2], ah1[3], st + A_OFF + aBase + 16 * RS_B + kb);
            ldsm4(al0[0], al0[1], al0[2], al0[3], st + AL_OFF + aBase + kb);
            ldsm4(al1[0], al1[1], al1[2], al1[3], st + AL_OFF + aBase + 16 * RS_B + kb);
            #pragma unroll
            for (int nt = 0; nt < 4; nt++) {
                uint32_t bh[4], bl[4];
                ldsm4(bh[0], bh[1], bh[2], bh[3], st + BH_OFF + bBase + nt * 16 * RS_B + kb);
                ldsm4(bl[0], bl[1], bl[2], bl[3], st + BL_OFF + bBase + nt * 16 * RS_B + kb);
                MMA(acc[0][2 * nt],     ah0, bh[0], bh[1]);
                MMA(acc[0][2 * nt + 1], ah0, bh[2], bh[3]);
                MMA(acc[1][2 * nt],     ah1, bh[0], bh[1]);
                MMA(acc[1][2 * nt + 1], ah1, bh[2], bh[3]);
                MMA(acc[0][2 * nt],     ah0, bl[0], bl[1]);
                MMA(acc[0][2 * nt + 1], ah0, bl[2], bl[3]);
                MMA(acc[1][2 * nt],     ah1, bl[0], bl[1]);
                MMA(acc[1][2 * nt + 1], ah1, bl[2], bl[3]);
                MMA(acc[0][2 * nt],     al0, bh[0], bh[1]);
                MMA(acc[0][2 * nt + 1], al0, bh[2], bh[3]);
                MMA(acc[1][2 * nt],     al1, bh[0], bh[1]);
                MMA(acc[1][2 * nt + 1], al1, bh[2], bh[3]);
            }
        }
        __syncthreads();
        if (c + 2 < NC) {
            load_stage(c + 2, c & 1);
            CPCOMMIT;
        }
    }

    // epilogue
    const int r0 = bm + wm + (lane >> 2);
    const int cb = n0 + wn + ((lane & 3) << 1);
    #pragma unroll
    for (int mt = 0; mt < 2; mt++) {
        #pragma unroll
        for (int nf = 0; nf < 8; nf++) {
            int col = cb + (nf << 3);
            if (col >= N) continue;
            float2 bv = *(const float2*)(bias + col);
            int row = r0 + (mt << 4);
            float v0 = acc[mt][nf][0] + bv.x, v1 = acc[mt][nf][1] + bv.y;
            float v2 = acc[mt][nf][2] + bv.x, v3 = acc[mt][nf][3] + bv.y;
            if (MODE == 1 || MODE == 2 || MODE == 3) {
                v0 = fmaxf(v0, 0.f); v1 = fmaxf(v1, 0.f);
                v2 = fmaxf(v2, 0.f); v3 = fmaxf(v3, 0.f);
            }
            if (MODE == 0 || MODE == 3) {
                *(float2*)(Cf + (size_t)row * ldc + col) = make_float2(v0, v1);
                *(float2*)(Cf + (size_t)(row + 8) * ldc + col) = make_float2(v2, v3);
            } else if (MODE == 2) {
                float2 o0 = *(const float2*)(Cf + (size_t)row * ldc + col);
                float2 o1 = *(const float2*)(Cf + (size_t)(row + 8) * ldc + col);
                *(float2*)(Cf + (size_t)row * ldc + col) = make_float2(o0.x + v0, o0.y + v1);
                *(float2*)(Cf + (size_t)(row + 8) * ldc + col) = make_float2(o1.x + v2, o1.y + v3);
            } else {  // MODE 1: split bf16 store
                __nv_bfloat16 h0, l0, h1, l1;
                split_bf16(v0, h0, l0);
                split_bf16(v1, h1, l1);
                size_t w0 = ((size_t)row * ldc + col) >> 1;
                ((uint32_t*)Ch)[w0] = pack2(h0, h1);
                ((uint32_t*)Cl)[w0] = pack2(l0, l1);
                split_bf16(v2, h0, l0);
                split_bf16(v3, h1, l1);
                size_t w1 = ((size_t)(row + 8) * ldc + col) >> 1;
                ((uint32_t*)Ch)[w1] = pack2(h0, h1);
                ((uint32_t*)Cl)[w1] = pack2(l0, l1);
            }
        }
    }
}

// ------------------------- BN / pooling ------------------------------------
__global__ void __launch_bounds__(320) k_bnstats() {
    int j = threadIdx.x;
    if (j >= HH) return;
    size_t r0 = (size_t)blockIdx.x * 64;
    float s = 0.f, ss = 0.f;
    for (int r = 0; r < 64; r++) {
        float v = g_z2[(r0 + r) * HH + j];
        s += v;
        ss += v * v;
    }
    atomicAdd(&g_stats[j], s);
    atomicAdd(&g_stats[HH + j], ss);
}

__global__ void k_bnapply(const float* __restrict__ scale, const float* __restrict__ bias,
                          int dorelu) {
    int j = threadIdx.x;
    if (j >= HH) return;
    const float invN = 1.f / (float)NN;
    float m = g_stats[j] * invN;
    float var = g_stats[HH + j] * invN - m * m;
    float co = rsqrtf(var + 1e-5f) * scale[j];
    float bi = bias[j];
    #pragma unroll
    for (int r = 0; r < 4; r++) {
        size_t o = (size_t)(blockIdx.x * 4 + r) * HH + j;
        float z = (g_z2[o] - m) * co + bi;
        if (dorelu) z = fmaxf(z, 0.f);
        g_h[o] += z;
    }
}

// vt[g] = vn[g] + sum of hv rows in graph g (batch sorted -> contiguous)
__global__ void k_vtgather() {
    int j = threadIdx.x;
    if (j >= HH) return;
    int g = blockIdx.x;
    float a = g_vn[(size_t)g * HH + j];
    int s0 = g_gstart[g], c = g_gcnt[g];
    for (int i = 0; i < c; i++) a += g_hv[(size_t)(s0 + i) * HH + j];
    g_vt[(size_t)g * HH + j] = a;
}

__global__ void k_poolgather() {
    int j = threadIdx.x;
    if (j >= HH) return;
    int g = blockIdx.x;
    float a = 0.f;
    int s0 = g_gstart[g], c = g_gcnt[g];
    for (int i = 0; i < c; i++) a += g_h[(size_t)(s0 + i) * HH + j];
    g_pool[(size_t)g * HH + j] = a;
}

// h_rep = [pooled_h | id_pool(analytic) | morgan | maccs | 0pad]
__global__ void k_assemble(const float* __restrict__ morgan, const float* __restrict__ maccs) {
    GSTRIDE(idx, GG * DGP) {
        int g = idx / DGP, c = idx % DGP;
        int cnt = g_gcnt[g];
        float denom = fmaxf((float)cnt, 1.f);
        float v;
        if (c < HH) {
            v = g_pool[(size_t)g * HH + c] / denom;
        } else if (c < HH + FF) {
            int f = c - HH;
            int cf = (f < cnt) ? ((cnt - 1 - f) / FF + 1) : 0;
            v = (float)cf / denom;
        } else if (c < HH + FF + 1024) {
            v = morgan[(size_t)g * 1024 + (c - HH - FF)];
        } else if (c < DGP - 1) {
            v = maccs[(size_t)g * 167 + (c - HH - FF - 1024)];
        } else {
            v = 0.f;
        }
        g_hrep[idx] = v;
    }
}

__global__ void __launch_bounds__(256)
k_final(const float* __restrict__ Wp2, const float* __restrict__ bp2,
        float* __restrict__ out) {
    int g = blockIdx.x;
    float acc = 0.f;
    for (int k = threadIdx.x; k < H2; k += blockDim.x)
        acc += g_ph[(size_t)g * H2 + k] * Wp2[k];
    __shared__ float smr[256];
    smr[threadIdx.x] = acc;
    __syncthreads();
    for (int s = 128; s > 0; s >>= 1) {
        if (threadIdx.x < s) smr[threadIdx.x] += smr[threadIdx.x + s];
        __syncthreads();
    }
    if (threadIdx.x == 0) out[g] = smr[0] + bp2[0];
}

// ---------------------------------------------------------------------------
static inline int nblk(long long work, int t) { return (int)((work + t - 1) / t); }

extern "C" void kernel_launch(void* const* d_in, const int* in_sizes, int n_in,
                              void* d_out, int out_size) {
    const void* ord[21];
    int p = 0;
    const int* edge = nullptr;
    const int* batch = nullptr;
    for (int i = 0; i < n_in; i++) {
        if (in_sizes[i] == 2 * EE) edge = (const int*)d_in[i];
        else if (in_sizes[i] == NN) batch = (const int*)d_in[i];
        else if (p < 21) ord[p++] = d_in[i];
    }
    const float* x        = (const float*)ord[0];
    const float* morgan   = (const float*)ord[1];
    const float* maccs    = (const float*)ord[2];
    const float* W_emb    = (const float*)ord[3];
    const float* b_emb    = (const float*)ord[4];
    const float* gin_W1   = (const float*)ord[5];
    const float* gin_b1   = (const float*)ord[6];
    const float* gin_W2   = (const float*)ord[7];
    const float* gin_b2   = (const float*)ord[8];
    const float* bn_scale = (const float*)ord[9];
    const float* bn_bias  = (const float*)ord[10];
    const float* eps      = (const float*)ord[11];
    const float* vn0      = (const float*)ord[12];
    const float* vn_W1    = (const float*)ord[13];
    const float* vn_b1    = (const float*)ord[14];
    const float* vn_W2    = (const float*)ord[15];
    const float* vn_b2    = (const float*)ord[16];
    const float* Wp1      = (const float*)ord[17];
    const float* bp1      = (const float*)ord[18];
    const float* Wp2      = (const float*)ord[19];
    const float* bp2      = (const float*)ord[20];
    const int* src = edge;
    const int* dst = edge + EE;
    float* out = (float*)d_out;

    float *pzin, *pz2, *pvt, *pvn, *pstats, *phrep, *pph;
    int *pdeg, *pgcnt;
    __nv_bfloat16 *pt1h, *pt1l, *pvhh, *pvhl;
    __nv_bfloat16 *pgW1h, *pgW1l, *pgW2h, *pgW2l, *pvW1h, *pvW1l, *pvW2h, *pvW2l, *pWph, *pWpl;
    cudaGetSymbolAddress((void**)&pzin, g_zin);
    cudaGetSymbolAddress((void**)&pz2, g_z2);
    cudaGetSymbolAddress((void**)&pvt, g_vt);
    cudaGetSymbolAddress((void**)&pvn, g_vn);
    cudaGetSymbolAddress((void**)&pstats, g_stats);
    cudaGetSymbolAddress((void**)&phrep, g_hrep);
    cudaGetSymbolAddress((void**)&pph, g_ph);
    cudaGetSymbolAddress((void**)&pdeg, g_deg);
    cudaGetSymbolAddress((void**)&pgcnt, g_gcnt);
    cudaGetSymbolAddress((void**)&pt1h, g_t1h);
    cudaGetSymbolAddress((void**)&pt1l, g_t1l);
    cudaGetSymbolAddress((void**)&pvhh, g_vhh);
    cudaGetSymbolAddress((void**)&pvhl, g_vhl);
    cudaGetSymbolAddress((void**)&pgW1h, g_gW1h);
    cudaGetSymbolAddress((void**)&pgW1l, g_gW1l);
    cudaGetSymbolAddress((void**)&pgW2h, g_gW2h);
    cudaGetSymbolAddress((void**)&pgW2l, g_gW2l);
    cudaGetSymbolAddress((void**)&pvW1h, g_vW1h);
    cudaGetSymbolAddress((void**)&pvW1l, g_vW1l);
    cudaGetSymbolAddress((void**)&pvW2h, g_vW2h);
    cudaGetSymbolAddress((void**)&pvW2l, g_vW2l);
    cudaGetSymbolAddress((void**)&pWph, g_Wph);
    cudaGetSymbolAddress((void**)&pWpl, g_Wpl);

    cudaFuncSetAttribute(k_mma<0, 0>, cudaFuncAttributeMaxDynamicSharedMemorySize, SMEMSZ);
    cudaFuncSetAttribute(k_mma<1, 1>, cudaFuncAttributeMaxDynamicSharedMemorySize, SMEMSZ);
    cudaFuncSetAttribute(k_mma<2, 0>, cudaFuncAttributeMaxDynamicSharedMemorySize, SMEMSZ);
    cudaFuncSetAttribute(k_mma<3, 1>, cudaFuncAttributeMaxDynamicSharedMemorySize, SMEMSZ);

    const int T = 256;

    // setup
    k_embed<<<NN / 4, 320>>>(x, W_emb, b_emb);
    k_initvn<<<nblk(GG * HH, T), T>>>(vn0);
    k_splitw<<<dim3(128, LL), T>>>(gin_W1, pgW1h, pgW1l, HH, H2, KP1);
    k_splitw<<<dim3(128, LL), T>>>(gin_W2, pgW2h, pgW2l, H2, HH, KP2);
    k_splitw<<<dim3(128, LL - 1), T>>>(vn_W1, pvW1h, pvW1l, HH, H2, KP1);
    k_splitw<<<dim3(128, LL - 1), T>>>(vn_W2, pvW2h, pvW2l, H2, HH, KP2);
    k_splitw<<<dim3(256, 1), T>>>(Wp1, pWph, pWpl, DGP - 1, H2, KPP);
    k_zero_i<<<nblk(NN, T), T>>>(pdeg, NN);
    k_zero_i<<<nblk(GG, T), T>>>(pgcnt, GG);
    k_histe<<<nblk(EE, T), T>>>(dst);
    k_histg<<<nblk(NN, T), T>>>(batch);
    k_scan_off<<<1, 1024>>>();
    k_scan_g<<<1, 1024>>>();
    k_scatter<<<nblk(EE, T), T>>>(src, dst);
    k_zero_pad<<<nblk(NN + GG, T), T>>>();

    for (int l = 0; l < LL; l++) {
        k_hv<<<NN / 4, 320>>>(batch);
        k_gather<<<NN, 320>>>(eps, l);

        k_mma<1, 1><<<dim3(5, NN / 128), 256, SMEMSZ>>>(
            pzin, nullptr, nullptr,
            pgW1h + (size_t)l * H2 * KP1, pgW1l + (size_t)l * H2 * KP1,
            gin_b1 + (size_t)l * H2, nullptr, pt1h, pt1l, HH, H2, KP2);
        k_mma<0, 0><<<dim3(3, NN / 128), 256, SMEMSZ>>>(
            nullptr, pt1h, pt1l,
            pgW2h + (size_t)l * HH * KP2, pgW2l + (size_t)l * HH * KP2,
            gin_b2 + (size_t)l * HH, pz2, nullptr, nullptr, KP2, HH, HH);

        k_zero_f<<<nblk(2 * HH, T), T>>>(pstats, 2 * HH);
        k_bnstats<<<NN / 64, 320>>>();
        k_bnapply<<<NN / 4, 320>>>(bn_scale + (size_t)l * HH,
                                   bn_bias + (size_t)l * HH, l < LL - 1 ? 1 : 0);

        if (l < LL - 1) {
            k_vtgather<<<GG, 320>>>();
            k_mma<1, 1><<<dim3(5, GG / 128), 256, SMEMSZ>>>(
                pvt, nullptr, nullptr,
                pvW1h + (size_t)l * H2 * KP1, pvW1l + (size_t)l * H2 * KP1,
                vn_b1 + (size_t)l * H2, nullptr, pvhh, pvhl, HH, H2, KP2);
            k_mma<2, 0><<<dim3(3, GG / 128), 256, SMEMSZ>>>(
                nullptr, pvhh, pvhl,
                pvW2h + (size_t)l * HH * KP2, pvW2l + (size_t)l * HH * KP2,
                vn_b2 + (size_t)l * HH, pvn, nullptr, nullptr, KP2, HH, HH);
        }
    }

    k_poolgather<<<GG, 320>>>();
    k_assemble<<<nblk(GG * DGP, T), T>>>(morgan, maccs);
    k_mma<3, 1><<<dim3(5, GG / 128), 256, SMEMSZ>>>(
        phrep, nullptr, nullptr, pWph, pWpl, bp1, pph, nullptr, nullptr, DGP, H2, H2);
    k_final<<<GG, 256>>>(Wp2, bp2, out);
}

// round 5
// speedup vs baseline: 2.5664x; 1.1064x over previous
#include <cuda_runtime.h>
#include <cuda_bf16.h>
#include <cstdint>
#include <cstddef>

#define NN 65536
#define EE 262144
#define GG 2048
#define DIN 9
#define HH 300
#define H2 600
#define FF 32
#define LL 5
#define KP1 320
#define KP2 608
#define KPP 1536
#define DGC 1523

// ---------------- scratch (device globals; no allocation allowed) ----------
static __device__ __align__(16) float g_h[(size_t)NN * HH];
static __device__ __align__(16) float g_z2[(size_t)NN * HH];
static __device__ __align__(16) float g_vn[(size_t)GG * HH];
static __device__ __align__(16) float g_pool[(size_t)GG * HH];
static __device__ float g_stats[2 * HH];
static __device__ float g_ph[(size_t)GG * H2];
static __device__ int g_deg[NN];
static __device__ int g_off[NN + 1];
static __device__ int g_cur[NN];
static __device__ int g_csr[EE];
static __device__ int g_gcnt[GG];
static __device__ int g_gstart[GG];

// split bf16 activation buffers (padded K strides)
static __device__ __align__(16) __nv_bfloat16 g_zinh[(size_t)NN * KP1];
static __device__ __align__(16) __nv_bfloat16 g_zinl[(size_t)NN * KP1];
static __device__ __align__(16) __nv_bfloat16 g_t1h[(size_t)NN * KP2];
static __device__ __align__(16) __nv_bfloat16 g_t1l[(size_t)NN * KP2];
static __device__ __align__(16) __nv_bfloat16 g_vth[(size_t)GG * KP1];
static __device__ __align__(16) __nv_bfloat16 g_vtl[(size_t)GG * KP1];
static __device__ __align__(16) __nv_bfloat16 g_vhh[(size_t)GG * KP2];
static __device__ __align__(16) __nv_bfloat16 g_vhl[(size_t)GG * KP2];
static __device__ __align__(16) __nv_bfloat16 g_hreph[(size_t)GG * KPP];
static __device__ __align__(16) __nv_bfloat16 g_hrepl[(size_t)GG * KPP];
// split transposed weights [L][N][Kp]
static __device__ __align__(16) __nv_bfloat16 g_gW1h[(size_t)LL * H2 * KP1];
static __device__ __align__(16) __nv_bfloat16 g_gW1l[(size_t)LL * H2 * KP1];
static __device__ __align__(16) __nv_bfloat16 g_gW2h[(size_t)LL * HH * KP2];
static __device__ __align__(16) __nv_bfloat16 g_gW2l[(size_t)LL * HH * KP2];
static __device__ __align__(16) __nv_bfloat16 g_vW1h[(size_t)(LL - 1) * H2 * KP1];
static __device__ __align__(16) __nv_bfloat16 g_vW1l[(size_t)(LL - 1) * H2 * KP1];
static __device__ __align__(16) __nv_bfloat16 g_vW2h[(size_t)(LL - 1) * HH * KP2];
static __device__ __align__(16) __nv_bfloat16 g_vW2l[(size_t)(LL - 1) * HH * KP2];
static __device__ __align__(16) __nv_bfloat16 g_Wph[(size_t)H2 * KPP];
static __device__ __align__(16) __nv_bfloat16 g_Wpl[(size_t)H2 * KPP];

#define GSTRIDE(i, n) for (int i = blockIdx.x * blockDim.x + threadIdx.x; \
                           i < (int)(n); i += gridDim.x * blockDim.x)

__device__ __forceinline__ void split_bf16(float v, __nv_bfloat16& hi, __nv_bfloat16& lo) {
    hi = __float2bfloat16_rn(v);
    lo = __float2bfloat16_rn(v - __bfloat162float(hi));
}
__device__ __forceinline__ uint32_t pack2(__nv_bfloat16 a, __nv_bfloat16 b) {
    __nv_bfloat162 t; t.x = a; t.y = b;
    return *(uint32_t*)&t;
}
// split a float4 and store 4 hi / 4 lo bf16 as uint2 each
__device__ __forceinline__ void split_store4(float4 v, __nv_bfloat16* ph, __nv_bfloat16* pl) {
    __nv_bfloat16 h0, l0, h1, l1, h2, l2, h3, l3;
    split_bf16(v.x, h0, l0);
    split_bf16(v.y, h1, l1);
    split_bf16(v.z, h2, l2);
    split_bf16(v.w, h3, l3);
    *(uint2*)ph = make_uint2(pack2(h0, h1), pack2(h2, h3));
    *(uint2*)pl = make_uint2(pack2(l0, l1), pack2(l2, l3));
}
__device__ __forceinline__ uint32_t smem_u32(const void* p) {
    uint32_t a;
    asm("{ .reg .u64 t; cvta.to.shared.u64 t, %1; cvt.u32.u64 %0, t; }" : "=r"(a) : "l"(p));
    return a;
}

// ------------------------- small kernels -----------------------------------
__global__ void k_zero_f(float* p, int n) { GSTRIDE(i, n) p[i] = 0.f; }
__global__ void k_zero_i(int* p, int n)   { GSTRIDE(i, n) p[i] = 0; }

__global__ void k_embed(const float* __restrict__ x, const float* __restrict__ W,
                        const float* __restrict__ b) {
    int j = threadIdx.x;
    if (j >= HH) return;
    float bj = b[j];
    #pragma unroll
    for (int r = 0; r < 4; r++) {
        int node = blockIdx.x * 4 + r;
        const float* xr = x + (size_t)node * DIN;
        float acc = bj;
        #pragma unroll
        for (int k = 0; k < DIN; k++) acc += xr[k] * W[k * HH + j];
        g_h[(size_t)node * HH + j] = acc;
    }
}

__global__ void k_initvn(const float* __restrict__ vn0) {
    GSTRIDE(idx, GG * HH) g_vn[idx] = vn0[idx % HH];
}

// fused: zin[n] = (1+eps)*(h[n]+vn[b[n]]) + sum_nb (h[s]+vn[b[s]]) -> split bf16
__global__ void __launch_bounds__(256) k_gather(const int* __restrict__ batch,
                                                const float* __restrict__ eps, int l) {
    int w = threadIdx.x >> 5, lane = threadIdx.x & 31;
    int n = (blockIdx.x << 3) + w;
    float e1 = 1.f + eps[l];
    const float4* h4 = (const float4*)g_h;
    const float4* vn4 = (const float4*)g_vn;
    int bn = batch[n];
    float4 acc[3];
    #pragma unroll
    for (int q = 0; q < 3; q++) {
        int idx = lane + (q << 5);
        if (idx < 75) {
            float4 a = h4[(size_t)n * 75 + idx];
            float4 v = vn4[(size_t)bn * 75 + idx];
            acc[q] = make_float4(e1 * (a.x + v.x), e1 * (a.y + v.y),
                                 e1 * (a.z + v.z), e1 * (a.w + v.w));
        }
    }
    int e0 = g_off[n], e1i = g_off[n + 1];
    for (int e = e0; e < e1i; e++) {
        int s = g_csr[e];
        int bs = batch[s];
        #pragma unroll
        for (int q = 0; q < 3; q++) {
            int idx = lane + (q << 5);
            if (idx < 75) {
                float4 a = h4[(size_t)s * 75 + idx];
                float4 v = vn4[(size_t)bs * 75 + idx];
                acc[q].x += a.x + v.x; acc[q].y += a.y + v.y;
                acc[q].z += a.z + v.z; acc[q].w += a.w + v.w;
            }
        }
    }
    #pragma unroll
    for (int q = 0; q < 3; q++) {
        int idx = lane + (q << 5);
        if (idx < 75)
            split_store4(acc[q], g_zinh + (size_t)n * KP1 + idx * 4,
                         g_zinl + (size_t)n * KP1 + idx * 4);
    }
}

// vt[g] = (cnt+1)*vn[g] + sum_{i in g} h_old[i] -> split bf16
__global__ void __launch_bounds__(256) k_vtgather() {
    int w = threadIdx.x >> 5, lane = threadIdx.x & 31;
    int g = (blockIdx.x << 3) + w;
    int s0 = g_gstart[g], c = g_gcnt[g];
    float cf = (float)(c + 1);
    const float4* h4 = (const float4*)g_h;
    const float4* vn4 = (const float4*)g_vn;
    float4 acc[3];
    #pragma unroll
    for (int q = 0; q < 3; q++) {
        int idx = lane + (q << 5);
        if (idx < 75) {
            float4 v = vn4[(size_t)g * 75 + idx];
            acc[q] = make_float4(cf * v.x, cf * v.y, cf * v.z, cf * v.w);
        }
    }
    for (int i = 0; i < c; i++) {
        size_t row = (size_t)(s0 + i) * 75;
        #pragma unroll
        for (int q = 0; q < 3; q++) {
            int idx = lane + (q << 5);
            if (idx < 75) {
                float4 a = h4[row + idx];
                acc[q].x += a.x; acc[q].y += a.y; acc[q].z += a.z; acc[q].w += a.w;
            }
        }
    }
    #pragma unroll
    for (int q = 0; q < 3; q++) {
        int idx = lane + (q << 5);
        if (idx < 75)
            split_store4(acc[q], g_vth + (size_t)g * KP1 + idx * 4,
                         g_vtl + (size_t)g * KP1 + idx * 4);
    }
}

__global__ void __launch_bounds__(256) k_poolgather() {
    int w = threadIdx.x >> 5, lane = threadIdx.x & 31;
    int g = (blockIdx.x << 3) + w;
    int s0 = g_gstart[g], c = g_gcnt[g];
    const float4* h4 = (const float4*)g_h;
    float4* p4 = (float4*)g_pool;
    float4 acc[3];
    #pragma unroll
    for (int q = 0; q < 3; q++) acc[q] = make_float4(0.f, 0.f, 0.f, 0.f);
    for (int i = 0; i < c; i++) {
        size_t row = (size_t)(s0 + i) * 75;
        #pragma unroll
        for (int q = 0; q < 3; q++) {
            int idx = lane + (q << 5);
            if (idx < 75) {
                float4 a = h4[row + idx];
                acc[q].x += a.x; acc[q].y += a.y; acc[q].z += a.z; acc[q].w += a.w;
            }
        }
    }
    #pragma unroll
    for (int q = 0; q < 3; q++) {
        int idx = lane + (q << 5);
        if (idx < 75) p4[(size_t)g * 75 + idx] = acc[q];
    }
}

// ---------------------- CSR / segment build --------------------------------
__global__ void k_histe(const int* __restrict__ dst) {
    GSTRIDE(e, EE) atomicAdd(&g_deg[dst[e]], 1);
}
__global__ void k_scatter(const int* __restrict__ src, const int* __restrict__ dst) {
    GSTRIDE(e, EE) {
        int pos = atomicAdd(&g_cur[dst[e]], 1);
        g_csr[pos] = src[e];
    }
}
__global__ void k_histg(const int* __restrict__ batch) {
    GSTRIDE(i, NN) atomicAdd(&g_gcnt[batch[i]], 1);
}
__global__ void __launch_bounds__(1024) k_scan_off() {
    __shared__ int sh[1024];
    int t = threadIdx.x;
    int base = t * 64;
    int s = 0;
    for (int i = 0; i < 64; i++) s += g_deg[base + i];
    sh[t] = s;
    __syncthreads();
    int mysum = s;
    for (int d = 1; d < 1024; d <<= 1) {
        int v = (t >= d) ? sh[t - d] : 0;
        __syncthreads();
        sh[t] += v;
        __syncthreads();
    }
    int off = sh[t] - mysum;
    for (int i = 0; i < 64; i++) {
        g_off[base + i] = off;
        g_cur[base + i] = off;
        off += g_deg[base + i];
    }
    if (t == 1023) g_off[NN] = off;
}
__global__ void __launch_bounds__(1024) k_scan_g() {
    __shared__ int sh[1024];
    int t = threadIdx.x;
    int a0 = g_gcnt[2 * t], a1 = g_gcnt[2 * t + 1];
    int s = a0 + a1;
    sh[t] = s;
    __syncthreads();
    for (int d = 1; d < 1024; d <<= 1) {
        int v = (t >= d) ? sh[t - d] : 0;
        __syncthreads();
        sh[t] += v;
        __syncthreads();
    }
    int off = sh[t] - s;
    g_gstart[2 * t] = off;
    g_gstart[2 * t + 1] = off + a0;
}

// ---------------------- weight splitting / padding --------------------------
__global__ void k_splitw(const float* __restrict__ W, __nv_bfloat16* __restrict__ oh,
                         __nv_bfloat16* __restrict__ ol, int K, int N, int Kp) {
    int l = blockIdx.y;
    const float* Ws = W + (size_t)l * K * N;
    __nv_bfloat16* ohs = oh + (size_t)l * N * Kp;
    __nv_bfloat16* ols = ol + (size_t)l * N * Kp;
    GSTRIDE(idx, N * Kp) {
        int n = idx / Kp, k = idx % Kp;
        float v = (k < K) ? Ws[(size_t)k * N + n] : 0.f;
        __nv_bfloat16 hi, lo;
        split_bf16(v, hi, lo);
        ohs[idx] = hi;
        ols[idx] = lo;
    }
}

// zero padding columns of zin (300..319), t1 (600..607), vt, vh
__global__ void k_zero_pads() {
    GSTRIDE(i, NN + GG) {
        if (i < NN) {
            #pragma unroll
            for (int q = 0; q < 5; q++) {
                *(uint2*)(g_zinh + (size_t)i * KP1 + HH + q * 4) = make_uint2(0, 0);
                *(uint2*)(g_zinl + (size_t)i * KP1 + HH + q * 4) = make_uint2(0, 0);
            }
            *(uint4*)(g_t1h + (size_t)i * KP2 + H2) = make_uint4(0, 0, 0, 0);
            *(uint4*)(g_t1l + (size_t)i * KP2 + H2) = make_uint4(0, 0, 0, 0);
        } else {
            int r = i - NN;
            #pragma unroll
            for (int q = 0; q < 5; q++) {
                *(uint2*)(g_vth + (size_t)r * KP1 + HH + q * 4) = make_uint2(0, 0);
                *(uint2*)(g_vtl + (size_t)r * KP1 + HH + q * 4) = make_uint2(0, 0);
            }
            *(uint4*)(g_vhh + (size_t)r * KP2 + H2) = make_uint4(0, 0, 0, 0);
            *(uint4*)(g_vhl + (size_t)r * KP2 + H2) = make_uint4(0, 0, 0, 0);
        }
    }
}

// ---------------------- mma.sync GEMM ---------------------------------------
// C[M,N] = epi(A[M,K] @ Bt[N,K]^T + bias). A,B pre-split bf16 (row stride K).
// MODE 0: fp32 store (+STATS). 1: relu -> split bf16. 2: Cf += relu. 3: relu fp32.
#define RS_B 80
#define A_OFF 0
#define AL_OFF 10240
#define BH_OFF 20480
#define BL_OFF 30720
#define STAGE 40960
#define SMEMSZ (2 * STAGE)

#define MMA(c, a, b0v, b1v) \
    asm volatile("mma.sync.aligned.m16n8k16.row.col.f32.bf16.bf16.f32 " \
                 "{%0,%1,%2,%3},{%4,%5,%6,%7},{%8,%9},{%0,%1,%2,%3};" \
                 : "+f"((c)[0]), "+f"((c)[1]), "+f"((c)[2]), "+f"((c)[3]) \
                 : "r"((a)[0]), "r"((a)[1]), "r"((a)[2]), "r"((a)[3]), \
                   "r"(b0v), "r"(b1v))
#define CP16(dst, src) \
    asm volatile("cp.async.cg.shared.global [%0], [%1], 16;" :: "r"(dst), "l"(src))
#define CPCOMMIT asm volatile("cp.async.commit_group;" ::: "memory")
#define CPWAIT1 asm volatile("cp.async.wait_group 1;" ::: "memory")
#define CPWAIT0 asm volatile("cp.async.wait_group 0;" ::: "memory")

__device__ __forceinline__ void ldsm4(uint32_t& r0, uint32_t& r1, uint32_t& r2,
                                      uint32_t& r3, uint32_t a) {
    asm volatile("ldmatrix.sync.aligned.m8n8.x4.shared.b16 {%0,%1,%2,%3}, [%4];"
                 : "=r"(r0), "=r"(r1), "=r"(r2), "=r"(r3) : "r"(a));
}

template <int MODE, int STATS>
__global__ void __launch_bounds__(256)
k_mma(const __nv_bfloat16* __restrict__ Ah, const __nv_bfloat16* __restrict__ Al,
      const __nv_bfloat16* __restrict__ Bh, const __nv_bfloat16* __restrict__ Bl,
      const float* __restrict__ bias, float* __restrict__ Cf,
      __nv_bfloat16* __restrict__ Ch, __nv_bfloat16* __restrict__ Cl,
      int K, int N, int ldc) {
    extern __shared__ __align__(16) char sm[];
    const uint32_t sb = smem_u32(sm);
    const int tid = threadIdx.x, wid = tid >> 5, lane = tid & 31;
    const int bm = blockIdx.y * 128, n0 = blockIdx.x * 128;
    const int NC = K >> 5;

    auto load_stage = [&](int c, int s) {
        char* bufc = sm + s * STAGE;
        uint32_t bufu = sb + s * STAGE;
        const int kh0 = c << 5;
        #pragma unroll
        for (int u = 0; u < 2; u++) {
            int idx = tid + (u << 8);
            int r = idx >> 2, kc = idx & 3;
            uint32_t doff = (uint32_t)r * RS_B + ((uint32_t)kc << 4);
            size_t go = (size_t)(bm + r) * K + kh0 + (kc << 3);
            CP16(bufu + A_OFF + doff, Ah + go);
            CP16(bufu + AL_OFF + doff, Al + go);
        }
        #pragma unroll
        for (int u = 0; u < 2; u++) {
            int idx = tid + (u << 8);
            int r = idx >> 2, kc = idx & 3;
            uint32_t doff = (uint32_t)r * RS_B + ((uint32_t)kc << 4);
            int gn = n0 + r;
            if (gn < N) {
                size_t go = (size_t)gn * K + kh0 + (kc << 3);
                CP16(bufu + BH_OFF + doff, Bh + go);
                CP16(bufu + BL_OFF + doff, Bl + go);
            } else {
                uint4 z = make_uint4(0, 0, 0, 0);
                *(uint4*)(bufc + BH_OFF + doff) = z;
                *(uint4*)(bufc + BL_OFF + doff) = z;
            }
        }
    };

    const int wm = (wid & 3) << 5, wn = (wid >> 2) << 6;
    const uint32_t aBase = (uint32_t)((wm + (lane & 15)) * RS_B + ((lane >> 4) << 4));
    const uint32_t bBase = (uint32_t)((wn + ((lane >> 4) << 3) + (lane & 7)) * RS_B +
                                      (((lane >> 3) & 1) << 4));

    float acc[2][8][4];
    #pragma unroll
    for (int a = 0; a < 2; a++)
        #pragma unroll
        for (int b = 0; b < 8; b++)
            #pragma unroll
            for (int q = 0; q < 4; q++) acc[a][b][q] = 0.f;

    load_stage(0, 0);
    CPCOMMIT;
    if (NC > 1) load_stage(1, 1);
    CPCOMMIT;

    for (int c = 0; c < NC; c++) {
        if (c == NC - 1) { CPWAIT0; } else { CPWAIT1; }
        __syncthreads();
        uint32_t st = sb + (c & 1) * STAGE;
        #pragma unroll
        for (int kb = 0; kb < 64; kb += 32) {
            uint32_t ah0[4], ah1[4], al0[4], al1[4];
            ldsm4(ah0[0], ah0[1], ah0[2], ah0[3], st + A_OFF + aBase + kb);
            ldsm4(ah1[0], ah1[1], ah1[2], ah1[3], st + A_OFF + aBase + 16 * RS_B + kb);
            ldsm4(al0[0], al0[1], al0[2], al0[3], st + AL_OFF + aBase + kb);
            ldsm4(al1[0], al1[1], al1[2], al1[3], st + AL_OFF + aBase + 16 * RS_B + kb);
            #pragma unroll
            for (int nt = 0; nt < 4; nt++) {
                uint32_t bh[4], bl[4];
                ldsm4(bh[0], bh[1], bh[2], bh[3], st + BH_OFF + bBase + nt * 16 * RS_B + kb);
                ldsm4(bl[0], bl[1], bl[2], bl[3], st + BL_OFF + bBase + nt * 16 * RS_B + kb);
                MMA(acc[0][2 * nt],     ah0, bh[0], bh[1]);
                MMA(acc[0][2 * nt + 1], ah0, bh[2], bh[3]);
                MMA(acc[1][2 * nt],     ah1, bh[0], bh[1]);
                MMA(acc[1][2 * nt + 1], ah1, bh[2], bh[3]);
                MMA(acc[0][2 * nt],     ah0, bl[0], bl[1]);
                MMA(acc[0][2 * nt + 1], ah0, bl[2], bl[3]);
                MMA(acc[1][2 * nt],     ah1, bl[0], bl[1]);
                MMA(acc[1][2 * nt + 1], ah1, bl[2], bl[3]);
                MMA(acc[0][2 * nt],     al0, bh[0], bh[1]);
                MMA(acc[0][2 * nt + 1], al0, bh[2], bh[3]);
                MMA(acc[1][2 * nt],     al1, bh[0], bh[1]);
                MMA(acc[1][2 * nt + 1], al1, bh[2], bh[3]);
            }
        }
        __syncthreads();
        if (c + 2 < NC) {
            load_stage(c + 2, c & 1);
            CPCOMMIT;
        }
    }

    // epilogue
    const int r0 = bm + wm + (lane >> 2);
    const int cb = n0 + wn + ((lane & 3) << 1);
    #pragma unroll
    for (int mt = 0; mt < 2; mt++) {
        #pragma unroll
        for (int nf = 0; nf < 8; nf++) {
            int col = cb + (nf << 3);
            if (col >= N) continue;
            float2 bv = *(const float2*)(bias + col);
            int row = r0 + (mt << 4);
            float v0 = acc[mt][nf][0] + bv.x, v1 = acc[mt][nf][1] + bv.y;
            float v2 = acc[mt][nf][2] + bv.x, v3 = acc[mt][nf][3] + bv.y;
            if (MODE == 1 || MODE == 2 || MODE == 3) {
                v0 = fmaxf(v0, 0.f); v1 = fmaxf(v1, 0.f);
                v2 = fmaxf(v2, 0.f); v3 = fmaxf(v3, 0.f);
            }
            if (MODE == 0 || MODE == 3) {
                *(float2*)(Cf + (size_t)row * ldc + col) = make_float2(v0, v1);
                *(float2*)(Cf + (size_t)(row + 8) * ldc + col) = make_float2(v2, v3);
            } else if (MODE == 2) {
                float2 o0 = *(const float2*)(Cf + (size_t)row * ldc + col);
                float2 o1 = *(const float2*)(Cf + (size_t)(row + 8) * ldc + col);
                *(float2*)(Cf + (size_t)row * ldc + col) = make_float2(o0.x + v0, o0.y + v1);
                *(float2*)(Cf + (size_t)(row + 8) * ldc + col) = make_float2(o1.x + v2, o1.y + v3);
            } else {
                __nv_bfloat16 h0, l0, h1, l1;
                split_bf16(v0, h0, l0);
                split_bf16(v1, h1, l1);
                size_t w0 = ((size_t)row * ldc + col) >> 1;
                ((uint32_t*)Ch)[w0] = pack2(h0, h1);
                ((uint32_t*)Cl)[w0] = pack2(l0, l1);
                split_bf16(v2, h0, l0);
                split_bf16(v3, h1, l1);
                size_t w1 = ((size_t)(row + 8) * ldc + col) >> 1;
                ((uint32_t*)Ch)[w1] = pack2(h0, h1);
                ((uint32_t*)Cl)[w1] = pack2(l0, l1);
            }
        }
    }
    if (STATS) {
        #pragma unroll
        for (int nf = 0; nf < 8; nf++) {
            int col = cb + (nf << 3);
            bool ok = col < N;
            float2 bv = ok ? *(const float2*)(bias + col) : make_float2(0.f, 0.f);
            float s0 = 0.f, q0 = 0.f, s1 = 0.f, q1 = 0.f;
            #pragma unroll
            for (int mt = 0; mt < 2; mt++) {
                float v0 = acc[mt][nf][0] + bv.x, v1 = acc[mt][nf][1] + bv.y;
                float v2 = acc[mt][nf][2] + bv.x, v3 = acc[mt][nf][3] + bv.y;
                s0 += v0 + v2; q0 += v0 * v0 + v2 * v2;
                s1 += v1 + v3; q1 += v1 * v1 + v3 * v3;
            }
            #pragma unroll
            for (int o = 4; o < 32; o <<= 1) {
                s0 += __shfl_xor_sync(0xFFFFFFFFu, s0, o);
                q0 += __shfl_xor_sync(0xFFFFFFFFu, q0, o);
                s1 += __shfl_xor_sync(0xFFFFFFFFu, s1, o);
                q1 += __shfl_xor_sync(0xFFFFFFFFu, q1, o);
            }
            if (lane < 4 && ok) {
                atomicAdd(&g_stats[col], s0);
                atomicAdd(&g_stats[col + 1], s1);
                atomicAdd(&g_stats[HH + col], q0);
                atomicAdd(&g_stats[HH + col + 1], q1);
            }
        }
    }
}

// ------------------------- BN apply -----------------------------------------
__global__ void k_bnapply(const float* __restrict__ scale, const float* __restrict__ bias,
                          int dorelu) {
    int j = threadIdx.x;
    if (j >= HH) return;
    const float invN = 1.f / (float)NN;
    float m = g_stats[j] * invN;
    float var = g_stats[HH + j] * invN - m * m;
    float co = rsqrtf(var + 1e-5f) * scale[j];
    float bi = bias[j];
    #pragma unroll
    for (int r = 0; r < 4; r++) {
        size_t o = (size_t)(blockIdx.x * 4 + r) * HH + j;
        float z = (g_z2[o] - m) * co + bi;
        if (dorelu) z = fmaxf(z, 0.f);
        g_h[o] += z;
    }
}

// h_rep split bf16 = [pooled_h | id_pool(analytic) | morgan | maccs | 0pad]
__global__ void k_assemble(const float* __restrict__ morgan, const float* __restrict__ maccs) {
    GSTRIDE(idx, GG * KPP) {
        int g = idx / KPP, c = idx % KPP;
        int cnt = g_gcnt[g];
        float denom = fmaxf((float)cnt, 1.f);
        float v;
        if (c < HH) {
            v = g_pool[(size_t)g * HH + c] / denom;
        } else if (c < HH + FF) {
            int f = c - HH;
            int cf = (f < cnt) ? ((cnt - 1 - f) / FF + 1) : 0;
            v = (float)cf / denom;
        } else if (c < HH + FF + 1024) {
            v = morgan[(size_t)g * 1024 + (c - HH - FF)];
        } else if (c < DGC) {
            v = maccs[(size_t)g * 167 + (c - HH - FF - 1024)];
        } else {
            v = 0.f;
        }
        __nv_bfloat16 hi, lo;
        split_bf16(v, hi, lo);
        g_hreph[idx] = hi;
        g_hrepl[idx] = lo;
    }
}

__global__ void __launch_bounds__(256)
k_final(const float* __restrict__ Wp2, const float* __restrict__ bp2,
        float* __restrict__ out) {
    int g = blockIdx.x;
    float acc = 0.f;
    for (int k = threadIdx.x; k < H2; k += blockDim.x)
        acc += g_ph[(size_t)g * H2 + k] * Wp2[k];
    __shared__ float smr[256];
    smr[threadIdx.x] = acc;
    __syncthreads();
    for (int s = 128; s > 0; s >>= 1) {
        if (threadIdx.x < s) smr[threadIdx.x] += smr[threadIdx.x + s];
        __syncthreads();
    }
    if (threadIdx.x == 0) out[g] = smr[0] + bp2[0];
}

// ---------------------------------------------------------------------------
static inline int nblk(long long work, int t) { return (int)((work + t - 1) / t); }

extern "C" void kernel_launch(void* const* d_in, const int* in_sizes, int n_in,
                              void* d_out, int out_size) {
    const void* ord[21];
    int p = 0;
    const int* edge = nullptr;
    const int* batch = nullptr;
    for (int i = 0; i < n_in; i++) {
        if (in_sizes[i] == 2 * EE) edge = (const int*)d_in[i];
        else if (in_sizes[i] == NN) batch = (const int*)d_in[i];
        else if (p < 21) ord[p++] = d_in[i];
    }
    const float* x        = (const float*)ord[0];
    const float* morgan   = (const float*)ord[1];
    const float* maccs    = (const float*)ord[2];
    const float* W_emb    = (const float*)ord[3];
    const float* b_emb    = (const float*)ord[4];
    const float* gin_W1   = (const float*)ord[5];
    const float* gin_b1   = (const float*)ord[6];
    const float* gin_W2   = (const float*)ord[7];
    const float* gin_b2   = (const float*)ord[8];
    const float* bn_scale = (const float*)ord[9];
    const float* bn_bias  = (const float*)ord[10];
    const float* eps      = (const float*)ord[11];
    const float* vn0      = (const float*)ord[12];
    const float* vn_W1    = (const float*)ord[13];
    const float* vn_b1    = (const float*)ord[14];
    const float* vn_W2    = (const float*)ord[15];
    const float* vn_b2    = (const float*)ord[16];
    const float* Wp1      = (const float*)ord[17];
    const float* bp1      = (const float*)ord[18];
    const float* Wp2      = (const float*)ord[19];
    const float* bp2      = (const float*)ord[20];
    const int* src = edge;
    const int* dst = edge + EE;
    float* out = (float*)d_out;

    float *pz2, *pvn, *pstats, *pph;
    int *pdeg, *pgcnt;
    __nv_bfloat16 *pzinh, *pzinl, *pt1h, *pt1l, *pvth, *pvtl, *pvhh, *pvhl, *phrh, *phrl;
    __nv_bfloat16 *pgW1h, *pgW1l, *pgW2h, *pgW2l, *pvW1h, *pvW1l, *pvW2h, *pvW2l, *pWph, *pWpl;
    cudaGetSymbolAddress((void**)&pz2, g_z2);
    cudaGetSymbolAddress((void**)&pvn, g_vn);
    cudaGetSymbolAddress((void**)&pstats, g_stats);
    cudaGetSymbolAddress((void**)&pph, g_ph);
    cudaGetSymbolAddress((void**)&pdeg, g_deg);
    cudaGetSymbolAddress((void**)&pgcnt, g_gcnt);
    cudaGetSymbolAddress((void**)&pzinh, g_zinh);
    cudaGetSymbolAddress((void**)&pzinl, g_zinl);
    cudaGetSymbolAddress((void**)&pt1h, g_t1h);
    cudaGetSymbolAddress((void**)&pt1l, g_t1l);
    cudaGetSymbolAddress((void**)&pvth, g_vth);
    cudaGetSymbolAddress((void**)&pvtl, g_vtl);
    cudaGetSymbolAddress((void**)&pvhh, g_vhh);
    cudaGetSymbolAddress((void**)&pvhl, g_vhl);
    cudaGetSymbolAddress((void**)&phrh, g_hreph);
    cudaGetSymbolAddress((void**)&phrl, g_hrepl);
    cudaGetSymbolAddress((void**)&pgW1h, g_gW1h);
    cudaGetSymbolAddress((void**)&pgW1l, g_gW1l);
    cudaGetSymbolAddress((void**)&pgW2h, g_gW2h);
    cudaGetSymbolAddress((void**)&pgW2l, g_gW2l);
    cudaGetSymbolAddress((void**)&pvW1h, g_vW1h);
    cudaGetSymbolAddress((void**)&pvW1l, g_vW1l);
    cudaGetSymbolAddress((void**)&pvW2h, g_vW2h);
    cudaGetSymbolAddress((void**)&pvW2l, g_vW2l);
    cudaGetSymbolAddress((void**)&pWph, g_Wph);
    cudaGetSymbolAddress((void**)&pWpl, g_Wpl);

    cudaFuncSetAttribute(k_mma<0, 1>, cudaFuncAttributeMaxDynamicSharedMemorySize, SMEMSZ);
    cudaFuncSetAttribute(k_mma<1, 0>, cudaFuncAttributeMaxDynamicSharedMemorySize, SMEMSZ);
    cudaFuncSetAttribute(k_mma<2, 0>, cudaFuncAttributeMaxDynamicSharedMemorySize, SMEMSZ);
    cudaFuncSetAttribute(k_mma<3, 0>, cudaFuncAttributeMaxDynamicSharedMemorySize, SMEMSZ);

    const int T = 256;

    // setup
    k_embed<<<NN / 4, 320>>>(x, W_emb, b_emb);
    k_initvn<<<nblk(GG * HH, T), T>>>(vn0);
    k_splitw<<<dim3(128, LL), T>>>(gin_W1, pgW1h, pgW1l, HH, H2, KP1);
    k_splitw<<<dim3(128, LL), T>>>(gin_W2, pgW2h, pgW2l, H2, HH, KP2);
    k_splitw<<<dim3(128, LL - 1), T>>>(vn_W1, pvW1h, pvW1l, HH, H2, KP1);
    k_splitw<<<dim3(128, LL - 1), T>>>(vn_W2, pvW2h, pvW2l, H2, HH, KP2);
    k_splitw<<<dim3(256, 1), T>>>(Wp1, pWph, pWpl, DGC, H2, KPP);
    k_zero_i<<<nblk(NN, T), T>>>(pdeg, NN);
    k_zero_i<<<nblk(GG, T), T>>>(pgcnt, GG);
    k_histe<<<nblk(EE, T), T>>>(dst);
    k_histg<<<nblk(NN, T), T>>>(batch);
    k_scan_off<<<1, 1024>>>();
    k_scan_g<<<1, 1024>>>();
    k_scatter<<<nblk(EE, T), T>>>(src, dst);
    k_zero_pads<<<nblk(NN + GG, T), T>>>();

    for (int l = 0; l < LL; l++) {
        k_gather<<<NN / 8, 256>>>(batch, eps, l);

        k_mma<1, 0><<<dim3(5, NN / 128), 256, SMEMSZ>>>(
            pzinh, pzinl,
            pgW1h + (size_t)l * H2 * KP1, pgW1l + (size_t)l * H2 * KP1,
            gin_b1 + (size_t)l * H2, nullptr, pt1h, pt1l, KP1, H2, KP2);
        k_zero_f<<<nblk(2 * HH, T), T>>>(pstats, 2 * HH);
        k_mma<0, 1><<<dim3(3, NN / 128), 256, SMEMSZ>>>(
            pt1h, pt1l,
            pgW2h + (size_t)l * HH * KP2, pgW2l + (size_t)l * HH * KP2,
            gin_b2 + (size_t)l * HH, pz2, nullptr, nullptr, KP2, HH, HH);

        if (l < LL - 1) k_vtgather<<<GG / 8, 256>>>();

        k_bnapply<<<NN / 4, 320>>>(bn_scale + (size_t)l * HH,
                                   bn_bias + (size_t)l * HH, l < LL - 1 ? 1 : 0);

        if (l < LL - 1) {
            k_mma<1, 0><<<dim3(5, GG / 128), 256, SMEMSZ>>>(
                pvth, pvtl,
                pvW1h + (size_t)l * H2 * KP1, pvW1l + (size_t)l * H2 * KP1,
                vn_b1 + (size_t)l * H2, nullptr, pvhh, pvhl, KP1, H2, KP2);
            k_mma<2, 0><<<dim3(3, GG / 128), 256, SMEMSZ>>>(
                pvhh, pvhl,
                pvW2h + (size_t)l * HH * KP2, pvW2l + (size_t)l * HH * KP2,
                vn_b2 + (size_t)l * HH, pvn, nullptr, nullptr, KP2, HH, HH);
        }
    }

    k_poolgather<<<GG / 8, 256>>>();
    k_assemble<<<nblk(GG * KPP, T), T>>>(morgan, maccs);
    k_mma<3, 0><<<dim3(5, GG / 128), 256, SMEMSZ>>>(
        phrh, phrl, pWph, pWpl, bp1, pph, nullptr, nullptr, KPP, H2, H2);
    k_final<<<GG, 256>>>(Wp2, bp2, out);
}

// round 6
// speedup vs baseline: 3.2927x; 1.2830x over previous
#include <cuda_runtime.h>
#include <cuda_bf16.h>
#include <cstdint>
#include <cstddef>

#define NN 65536
#define EE 262144
#define GG 2048
#define DIN 9
#define HH 300
#define H2 600
#define FF 32
#define LL 5
#define KP1 320
#define KP2 608
#define KPP 1536
#define DGC 1523

// ---------------- scratch (device globals; no allocation allowed) ----------
static __device__ __align__(16) float g_h[(size_t)NN * HH];
static __device__ __align__(16) float g_z2[(size_t)NN * HH];
static __device__ __align__(16) float g_vn[(size_t)GG * HH];
static __device__ __align__(16) float g_pool[(size_t)GG * HH];
static __device__ float g_stats[2 * HH];
static __device__ int g_deg[NN];
static __device__ int g_off[NN + 1];
static __device__ int g_cur[NN];
static __device__ int g_csr[EE];
static __device__ int g_gcnt[GG];
static __device__ int g_gstart[GG];

// split bf16 activation buffers (padded K strides)
static __device__ __align__(16) __nv_bfloat16 g_zinh[(size_t)NN * KP1];
static __device__ __align__(16) __nv_bfloat16 g_zinl[(size_t)NN * KP1];
static __device__ __align__(16) __nv_bfloat16 g_t1h[(size_t)NN * KP2];
static __device__ __align__(16) __nv_bfloat16 g_t1l[(size_t)NN * KP2];
static __device__ __align__(16) __nv_bfloat16 g_vth[(size_t)GG * KP1];
static __device__ __align__(16) __nv_bfloat16 g_vtl[(size_t)GG * KP1];
static __device__ __align__(16) __nv_bfloat16 g_vhh[(size_t)GG * KP2];
static __device__ __align__(16) __nv_bfloat16 g_vhl[(size_t)GG * KP2];
static __device__ __align__(16) __nv_bfloat16 g_hreph[(size_t)GG * KPP];
static __device__ __align__(16) __nv_bfloat16 g_hrepl[(size_t)GG * KPP];
// split transposed weights [L][N][Kp]
static __device__ __align__(16) __nv_bfloat16 g_gW1h[(size_t)LL * H2 * KP1];
static __device__ __align__(16) __nv_bfloat16 g_gW1l[(size_t)LL * H2 * KP1];
static __device__ __align__(16) __nv_bfloat16 g_gW2h[(size_t)LL * HH * KP2];
static __device__ __align__(16) __nv_bfloat16 g_gW2l[(size_t)LL * HH * KP2];
static __device__ __align__(16) __nv_bfloat16 g_vW1h[(size_t)(LL - 1) * H2 * KP1];
static __device__ __align__(16) __nv_bfloat16 g_vW1l[(size_t)(LL - 1) * H2 * KP1];
static __device__ __align__(16) __nv_bfloat16 g_vW2h[(size_t)(LL - 1) * HH * KP2];
static __device__ __align__(16) __nv_bfloat16 g_vW2l[(size_t)(LL - 1) * HH * KP2];
static __device__ __align__(16) __nv_bfloat16 g_Wph[(size_t)H2 * KPP];
static __device__ __align__(16) __nv_bfloat16 g_Wpl[(size_t)H2 * KPP];

#define GSTRIDE(i, n) for (int i = blockIdx.x * blockDim.x + threadIdx.x; \
                           i < (int)(n); i += gridDim.x * blockDim.x)

__device__ __forceinline__ void split_bf16(float v, __nv_bfloat16& hi, __nv_bfloat16& lo) {
    hi = __float2bfloat16_rn(v);
    lo = __float2bfloat16_rn(v - __bfloat162float(hi));
}
__device__ __forceinline__ uint32_t pack2(__nv_bfloat16 a, __nv_bfloat16 b) {
    __nv_bfloat162 t; t.x = a; t.y = b;
    return *(uint32_t*)&t;
}
__device__ __forceinline__ void split_store4(float4 v, __nv_bfloat16* ph, __nv_bfloat16* pl) {
    __nv_bfloat16 h0, l0, h1, l1, h2, l2, h3, l3;
    split_bf16(v.x, h0, l0);
    split_bf16(v.y, h1, l1);
    split_bf16(v.z, h2, l2);
    split_bf16(v.w, h3, l3);
    *(uint2*)ph = make_uint2(pack2(h0, h1), pack2(h2, h3));
    *(uint2*)pl = make_uint2(pack2(l0, l1), pack2(l2, l3));
}
__device__ __forceinline__ uint32_t smem_u32(const void* p) {
    uint32_t a;
    asm("{ .reg .u64 t; cvta.to.shared.u64 t, %1; cvt.u32.u64 %0, t; }" : "=r"(a) : "l"(p));
    return a;
}

// ------------------------- small kernels -----------------------------------
__global__ void k_embed(const float* __restrict__ x, const float* __restrict__ W,
                        const float* __restrict__ b) {
    int j = threadIdx.x;
    if (j >= HH) return;
    float bj = b[j];
    #pragma unroll
    for (int r = 0; r < 4; r++) {
        int node = blockIdx.x * 4 + r;
        const float* xr = x + (size_t)node * DIN;
        float acc = bj;
        #pragma unroll
        for (int k = 0; k < DIN; k++) acc += xr[k] * W[k * HH + j];
        g_h[(size_t)node * HH + j] = acc;
    }
}

__global__ void k_initvn(const float* __restrict__ vn0) {
    GSTRIDE(idx, GG * HH) g_vn[idx] = vn0[idx % HH];
}

__global__ void k_initout(const float* __restrict__ bp2, float* __restrict__ out) {
    GSTRIDE(i, GG) out[i] = bp2[0];
}

// fused: zin[n] = (1+eps)*(h[n]+vn[b[n]]) + sum_nb (h[s]+vn[b[s]]) -> split bf16
// block 0 additionally zeroes the BN stats accumulator.
__global__ void __launch_bounds__(256) k_gather(const int* __restrict__ batch,
                                                const float* __restrict__ eps, int l) {
    if (blockIdx.x == 0) {
        for (int i = threadIdx.x; i < 2 * HH; i += 256) g_stats[i] = 0.f;
    }
    int w = threadIdx.x >> 5, lane = threadIdx.x & 31;
    int n = (blockIdx.x << 3) + w;
    float e1 = 1.f + eps[l];
    const float4* h4 = (const float4*)g_h;
    const float4* vn4 = (const float4*)g_vn;
    int bn = batch[n];
    float4 acc[3];
    #pragma unroll
    for (int q = 0; q < 3; q++) {
        int idx = lane + (q << 5);
        if (idx < 75) {
            float4 a = h4[(size_t)n * 75 + idx];
            float4 v = vn4[(size_t)bn * 75 + idx];
            acc[q] = make_float4(e1 * (a.x + v.x), e1 * (a.y + v.y),
                                 e1 * (a.z + v.z), e1 * (a.w + v.w));
        }
    }
    int e0 = g_off[n], e1i = g_off[n + 1];
    for (int e = e0; e < e1i; e++) {
        int s = g_csr[e];
        int bs = batch[s];
        #pragma unroll
        for (int q = 0; q < 3; q++) {
            int idx = lane + (q << 5);
            if (idx < 75) {
                float4 a = h4[(size_t)s * 75 + idx];
                float4 v = vn4[(size_t)bs * 75 + idx];
                acc[q].x += a.x + v.x; acc[q].y += a.y + v.y;
                acc[q].z += a.z + v.z; acc[q].w += a.w + v.w;
            }
        }
    }
    #pragma unroll
    for (int q = 0; q < 3; q++) {
        int idx = lane + (q << 5);
        if (idx < 75)
            split_store4(acc[q], g_zinh + (size_t)n * KP1 + idx * 4,
                         g_zinl + (size_t)n * KP1 + idx * 4);
    }
}

// vt[g] = (cnt+1)*vn[g] + sum_{i in g} h_old[i] -> split bf16
__global__ void __launch_bounds__(256) k_vtgather() {
    int w = threadIdx.x >> 5, lane = threadIdx.x & 31;
    int g = (blockIdx.x << 3) + w;
    int s0 = g_gstart[g], c = g_gcnt[g];
    float cf = (float)(c + 1);
    const float4* h4 = (const float4*)g_h;
    const float4* vn4 = (const float4*)g_vn;
    float4 acc[3];
    #pragma unroll
    for (int q = 0; q < 3; q++) {
        int idx = lane + (q << 5);
        if (idx < 75) {
            float4 v = vn4[(size_t)g * 75 + idx];
            acc[q] = make_float4(cf * v.x, cf * v.y, cf * v.z, cf * v.w);
        }
    }
    for (int i = 0; i < c; i++) {
        size_t row = (size_t)(s0 + i) * 75;
        #pragma unroll
        for (int q = 0; q < 3; q++) {
            int idx = lane + (q << 5);
            if (idx < 75) {
                float4 a = h4[row + idx];
                acc[q].x += a.x; acc[q].y += a.y; acc[q].z += a.z; acc[q].w += a.w;
            }
        }
    }
    #pragma unroll
    for (int q = 0; q < 3; q++) {
        int idx = lane + (q << 5);
        if (idx < 75)
            split_store4(acc[q], g_vth + (size_t)g * KP1 + idx * 4,
                         g_vtl + (size_t)g * KP1 + idx * 4);
    }
}

__global__ void __launch_bounds__(256) k_poolgather() {
    int w = threadIdx.x >> 5, lane = threadIdx.x & 31;
    int g = (blockIdx.x << 3) + w;
    int s0 = g_gstart[g], c = g_gcnt[g];
    const float4* h4 = (const float4*)g_h;
    float4* p4 = (float4*)g_pool;
    float4 acc[3];
    #pragma unroll
    for (int q = 0; q < 3; q++) acc[q] = make_float4(0.f, 0.f, 0.f, 0.f);
    for (int i = 0; i < c; i++) {
        size_t row = (size_t)(s0 + i) * 75;
        #pragma unroll
        for (int q = 0; q < 3; q++) {
            int idx = lane + (q << 5);
            if (idx < 75) {
                float4 a = h4[row + idx];
                acc[q].x += a.x; acc[q].y += a.y; acc[q].z += a.z; acc[q].w += a.w;
            }
        }
    }
    #pragma unroll
    for (int q = 0; q < 3; q++) {
        int idx = lane + (q << 5);
        if (idx < 75) p4[(size_t)g * 75 + idx] = acc[q];
    }
}

// ---------------------- CSR / segment build --------------------------------
__global__ void k_zero_setup() {
    GSTRIDE(i, NN + GG) {
        if (i < NN) g_deg[i] = 0;
        else g_gcnt[i - NN] = 0;
    }
}
__global__ void k_hist(const int* __restrict__ dst, const int* __restrict__ batch) {
    GSTRIDE(e, EE) atomicAdd(&g_deg[dst[e]], 1);
    GSTRIDE(i, NN) atomicAdd(&g_gcnt[batch[i]], 1);
}
__global__ void k_scatter(const int* __restrict__ src, const int* __restrict__ dst) {
    GSTRIDE(e, EE) {
        int pos = atomicAdd(&g_cur[dst[e]], 1);
        g_csr[pos] = src[e];
    }
}
// single-block warp-coalesced exclusive scan of g_deg[65536] -> g_off, g_cur
__global__ void __launch_bounds__(1024) k_scan_off() {
    __shared__ int wsum[32];
    int t = threadIdx.x, w = t >> 5, lane = t & 31;
    int base = w * 2048;
    int s = 0;
    for (int k = 0; k < 64; k++) s += g_deg[base + k * 32 + lane];
    #pragma unroll
    for (int o = 16; o; o >>= 1) s += __shfl_xor_sync(0xFFFFFFFFu, s, o);
    if (!lane) wsum[w] = s;
    __syncthreads();
    if (w == 0) {
        int v = wsum[lane];
        int ex = v;
        #pragma unroll
        for (int o = 1; o < 32; o <<= 1) {
            int u = __shfl_up_sync(0xFFFFFFFFu, ex, o);
            if (lane >= o) ex += u;
        }
        if (lane == 31) g_off[NN] = ex;
        wsum[lane] = ex - v;
    }
    __syncthreads();
    int carry = wsum[w];
    for (int k = 0; k < 64; k++) {
        int v = g_deg[base + k * 32 + lane];
        int inc = v;
        #pragma unroll
        for (int o = 1; o < 32; o <<= 1) {
            int u = __shfl_up_sync(0xFFFFFFFFu, inc, o);
            if (lane >= o) inc += u;
        }
        int ex = carry + inc - v;
        g_off[base + k * 32 + lane] = ex;
        g_cur[base + k * 32 + lane] = ex;
        carry += __shfl_sync(0xFFFFFFFFu, inc, 31);
    }
}
__global__ void __launch_bounds__(1024) k_scan_g() {
    __shared__ int sh[1024];
    int t = threadIdx.x;
    int a0 = g_gcnt[2 * t], a1 = g_gcnt[2 * t + 1];
    int s = a0 + a1;
    sh[t] = s;
    __syncthreads();
    for (int d = 1; d < 1024; d <<= 1) {
        int v = (t >= d) ? sh[t - d] : 0;
        __syncthreads();
        sh[t] += v;
        __syncthreads();
    }
    int off = sh[t] - s;
    g_gstart[2 * t] = off;
    g_gstart[2 * t + 1] = off + a0;
}

// ---------------------- weight splitting (all in one launch) ----------------
__device__ __forceinline__ void splitw_seg(const float* W, __nv_bfloat16* oh,
                                           __nv_bfloat16* ol, int K, int Nn, int Kp) {
    GSTRIDE(idx, Nn * Kp) {
        int n = idx / Kp, k = idx % Kp;
        float v = (k < K) ? W[(size_t)k * Nn + n] : 0.f;
        __nv_bfloat16 hi, lo;
        split_bf16(v, hi, lo);
        oh[idx] = hi;
        ol[idx] = lo;
    }
}
__global__ void k_splitw_all(const float* __restrict__ gW1, const float* __restrict__ gW2,
                             const float* __restrict__ vW1, const float* __restrict__ vW2,
                             const float* __restrict__ Wp1) {
    int y = blockIdx.y;
    if (y < LL) {
        splitw_seg(gW1 + (size_t)y * HH * H2, g_gW1h + (size_t)y * H2 * KP1,
                   g_gW1l + (size_t)y * H2 * KP1, HH, H2, KP1);
    } else if (y < 2 * LL) {
        int l = y - LL;
        splitw_seg(gW2 + (size_t)l * H2 * HH, g_gW2h + (size_t)l * HH * KP2,
                   g_gW2l + (size_t)l * HH * KP2, H2, HH, KP2);
    } else if (y < 2 * LL + 4) {
        int l = y - 2 * LL;
        splitw_seg(vW1 + (size_t)l * HH * H2, g_vW1h + (size_t)l * H2 * KP1,
                   g_vW1l + (size_t)l * H2 * KP1, HH, H2, KP1);
    } else if (y < 2 * LL + 8) {
        int l = y - 2 * LL - 4;
        splitw_seg(vW2 + (size_t)l * H2 * HH, g_vW2h + (size_t)l * HH * KP2,
                   g_vW2l + (size_t)l * HH * KP2, H2, HH, KP2);
    } else {
        splitw_seg(Wp1, g_Wph, g_Wpl, DGC, H2, KPP);
    }
}

// zero padding columns of zin (300..319), t1 (600..607), vt, vh
__global__ void k_zero_pads() {
    GSTRIDE(i, NN + GG) {
        if (i < NN) {
            #pragma unroll
            for (int q = 0; q < 5; q++) {
                *(uint2*)(g_zinh + (size_t)i * KP1 + HH + q * 4) = make_uint2(0, 0);
                *(uint2*)(g_zinl + (size_t)i * KP1 + HH + q * 4) = make_uint2(0, 0);
            }
            *(uint4*)(g_t1h + (size_t)i * KP2 + H2) = make_uint4(0, 0, 0, 0);
            *(uint4*)(g_t1l + (size_t)i * KP2 + H2) = make_uint4(0, 0, 0, 0);
        } else {
            int r = i - NN;
            #pragma unroll
            for (int q = 0; q < 5; q++) {
                *(uint2*)(g_vth + (size_t)r * KP1 + HH + q * 4) = make_uint2(0, 0);
                *(uint2*)(g_vtl + (size_t)r * KP1 + HH + q * 4) = make_uint2(0, 0);
            }
            *(uint4*)(g_vhh + (size_t)r * KP2 + H2) = make_uint4(0, 0, 0, 0);
            *(uint4*)(g_vhl + (size_t)r * KP2 + H2) = make_uint4(0, 0, 0, 0);
        }
    }
}

// ---------------------- mma.sync GEMM (two-region merged) -------------------
// CFG 0: relu -> split bf16 out (region1: t1, region2: vh)
// CFG 1: region1 fp32 store + BN stats; region2: F2 += relu (vn update)
// CFG 2: predictor: relu, dot with Wp2 (=bias2), atomicAdd into out (=F2)
#define RS_B 80
#define A_OFF 0
#define AL_OFF 10240
#define BH_OFF 20480
#define BL_OFF 30720
#define STAGE 40960
#define SMEMSZ (2 * STAGE)

#define MMA(c, a, b0v, b1v) \
    asm volatile("mma.sync.aligned.m16n8k16.row.col.f32.bf16.bf16.f32 " \
                 "{%0,%1,%2,%3},{%4,%5,%6,%7},{%8,%9},{%0,%1,%2,%3};" \
                 : "+f"((c)[0]), "+f"((c)[1]), "+f"((c)[2]), "+f"((c)[3]) \
                 : "r"((a)[0]), "r"((a)[1]), "r"((a)[2]), "r"((a)[3]), \
                   "r"(b0v), "r"(b1v))
#define CP16(dst, src) \
    asm volatile("cp.async.cg.shared.global [%0], [%1], 16;" :: "r"(dst), "l"(src))
#define CPCOMMIT asm volatile("cp.async.commit_group;" ::: "memory")
#define CPWAIT1 asm volatile("cp.async.wait_group 1;" ::: "memory")
#define CPWAIT0 asm volatile("cp.async.wait_group 0;" ::: "memory")

__device__ __forceinline__ void ldsm4(uint32_t& r0, uint32_t& r1, uint32_t& r2,
                                      uint32_t& r3, uint32_t a) {
    asm volatile("ldmatrix.sync.aligned.m8n8.x4.shared.b16 {%0,%1,%2,%3}, [%4];"
                 : "=r"(r0), "=r"(r1), "=r"(r2), "=r"(r3) : "r"(a));
}

template <int CFG>
__global__ void __launch_bounds__(256)
k_mma(const __nv_bfloat16* __restrict__ Ah1, const __nv_bfloat16* __restrict__ Al1,
      const __nv_bfloat16* __restrict__ Bh1, const __nv_bfloat16* __restrict__ Bl1,
      const float* __restrict__ bias1, float* __restrict__ F1,
      __nv_bfloat16* __restrict__ H1, __nv_bfloat16* __restrict__ L1,
      const __nv_bfloat16* __restrict__ Ah2, const __nv_bfloat16* __restrict__ Al2,
      const __nv_bfloat16* __restrict__ Bh2, const __nv_bfloat16* __restrict__ Bl2,
      const float* __restrict__ bias2, float* __restrict__ F2,
      __nv_bfloat16* __restrict__ H2o, __nv_bfloat16* __restrict__ L2o,
      int My1, int K, int N, int ldc) {
    extern __shared__ __align__(16) char sm[];
    const uint32_t sb = smem_u32(sm);
    const int tid = threadIdx.x, wid = tid >> 5, lane = tid & 31;
    const bool rg2 = (int)blockIdx.y >= My1;
    const int by = rg2 ? (int)blockIdx.y - My1 : (int)blockIdx.y;
    const __nv_bfloat16* Ah = rg2 ? Ah2 : Ah1;
    const __nv_bfloat16* Al = rg2 ? Al2 : Al1;
    const __nv_bfloat16* Bh = rg2 ? Bh2 : Bh1;
    const __nv_bfloat16* Bl = rg2 ? Bl2 : Bl1;
    const float* bias = rg2 ? bias2 : bias1;
    const int bm = by << 7, n0 = (int)blockIdx.x << 7;
    const int NC = K >> 5;
    const int nv = (N - n0) < 128 ? (N - n0) : 128;

    auto load_stage = [&](int c, int s) {
        char* bufc = sm + s * STAGE;
        uint32_t bufu = sb + s * STAGE;
        const int kh0 = c << 5;
        #pragma unroll
        for (int u = 0; u < 2; u++) {
            int idx = tid + (u << 8);
            int r = idx >> 2, kc = idx & 3;
            uint32_t doff = (uint32_t)r * RS_B + ((uint32_t)kc << 4);
            size_t go = (size_t)(bm + r) * K + kh0 + (kc << 3);
            CP16(bufu + A_OFF + doff, Ah + go);
            CP16(bufu + AL_OFF + doff, Al + go);
        }
        #pragma unroll
        for (int u = 0; u < 2; u++) {
            int idx = tid + (u << 8);
            int r = idx >> 2, kc = idx & 3;
            uint32_t doff = (uint32_t)r * RS_B + ((uint32_t)kc << 4);
            int gn = n0 + r;
            if (gn < N) {
                size_t go = (size_t)gn * K + kh0 + (kc << 3);
                CP16(bufu + BH_OFF + doff, Bh + go);
                CP16(bufu + BL_OFF + doff, Bl + go);
            } else {
                uint4 z = make_uint4(0, 0, 0, 0);
                *(uint4*)(bufc + BH_OFF + doff) = z;
                *(uint4*)(bufc + BL_OFF + doff) = z;
            }
        }
    };

    const int wm = (wid & 3) << 5, wn = (wid >> 2) << 6;
    const int wrem = nv - wn;  // valid cols for this warp's 64-col tile
    const uint32_t aBase = (uint32_t)((wm + (lane & 15)) * RS_B + ((lane >> 4) << 4));
    const uint32_t bBase = (uint32_t)((wn + ((lane >> 4) << 3) + (lane & 7)) * RS_B +
                                      (((lane >> 3) & 1) << 4));

    float acc[2][8][4];
    #pragma unroll
    for (int a = 0; a < 2; a++)
        #pragma unroll
        for (int b = 0; b < 8; b++)
            #pragma unroll
            for (int q = 0; q < 4; q++) acc[a][b][q] = 0.f;

    load_stage(0, 0);
    CPCOMMIT;
    if (NC > 1) load_stage(1, 1);
    CPCOMMIT;

    for (int c = 0; c < NC; c++) {
        if (c == NC - 1) { CPWAIT0; } else { CPWAIT1; }
        __syncthreads();
        uint32_t st = sb + (c & 1) * STAGE;
        if (wrem > 0) {
            #pragma unroll
            for (int kb = 0; kb < 64; kb += 32) {
                uint32_t ah0[4], ah1[4], al0[4], al1[4];
                ldsm4(ah0[0], ah0[1], ah0[2], ah0[3], st + A_OFF + aBase + kb);
                ldsm4(ah1[0], ah1[1], ah1[2], ah1[3], st + A_OFF + aBase + 16 * RS_B + kb);
                ldsm4(al0[0], al0[1], al0[2], al0[3], st + AL_OFF + aBase + kb);
                ldsm4(al1[0], al1[1], al1[2], al1[3], st + AL_OFF + aBase + 16 * RS_B + kb);
                #pragma unroll
                for (int nt = 0; nt < 4; nt++) {
                    if (nt * 16 < wrem) {
                        uint32_t bh[4], bl[4];
                        ldsm4(bh[0], bh[1], bh[2], bh[3],
                              st + BH_OFF + bBase + nt * 16 * RS_B + kb);
                        ldsm4(bl[0], bl[1], bl[2], bl[3],
                              st + BL_OFF + bBase + nt * 16 * RS_B + kb);
                        MMA(acc[0][2 * nt],     ah0, bh[0], bh[1]);
                        MMA(acc[0][2 * nt + 1], ah0, bh[2], bh[3]);
                        MMA(acc[1][2 * nt],     ah1, bh[0], bh[1]);
                        MMA(acc[1][2 * nt + 1], ah1, bh[2], bh[3]);
                        MMA(acc[0][2 * nt],     ah0, bl[0], bl[1]);
                        MMA(acc[0][2 * nt + 1], ah0, bl[2], bl[3]);
                        MMA(acc[1][2 * nt],     ah1, bl[0], bl[1]);
                        MMA(acc[1][2 * nt + 1], ah1, bl[2], bl[3]);
                        MMA(acc[0][2 * nt],     al0, bh[0], bh[1]);
                        MMA(acc[0][2 * nt + 1], al0, bh[2], bh[3]);
                        MMA(acc[1][2 * nt],     al1, bh[0], bh[1]);
                        MMA(acc[1][2 * nt + 1], al1, bh[2], bh[3]);
                    }
                }
            }
        }
        __syncthreads();
        if (c + 2 < NC) {
            load_stage(c + 2, c & 1);
            CPCOMMIT;
        }
    }

    // epilogue
    const int r0 = bm + wm + (lane >> 2);
    const int cbl = n0 + wn + ((lane & 3) << 1);
    if (CFG == 0) {
        __nv_bfloat16* Ch = rg2 ? H2o : H1;
        __nv_bfloat16* Cl = rg2 ? L2o : L1;
        #pragma unroll
        for (int mt = 0; mt < 2; mt++) {
            #pragma unroll
            for (int nf = 0; nf < 8; nf++) {
                int col = cbl + (nf << 3);
                if (col >= N) continue;
                float2 bv = *(const float2*)(bias + col);
                int row = r0 + (mt << 4);
                float v0 = fmaxf(acc[mt][nf][0] + bv.x, 0.f);
                float v1 = fmaxf(acc[mt][nf][1] + bv.y, 0.f);
                float v2 = fmaxf(acc[mt][nf][2] + bv.x, 0.f);
                float v3 = fmaxf(acc[mt][nf][3] + bv.y, 0.f);
                __nv_bfloat16 h0, l0, h1, l1;
                split_bf16(v0, h0, l0);
                split_bf16(v1, h1, l1);
                size_t w0 = ((size_t)row * ldc + col) >> 1;
                ((uint32_t*)Ch)[w0] = pack2(h0, h1);
                ((uint32_t*)Cl)[w0] = pack2(l0, l1);
                split_bf16(v2, h0, l0);
                split_bf16(v3, h1, l1);
                size_t w1 = ((size_t)(row + 8) * ldc + col) >> 1;
                ((uint32_t*)Ch)[w1] = pack2(h0, h1);
                ((uint32_t*)Cl)[w1] = pack2(l0, l1);
            }
        }
    } else if (CFG == 1) {
        if (!rg2) {
            #pragma unroll
            for (int mt = 0; mt < 2; mt++) {
                #pragma unroll
                for (int nf = 0; nf < 8; nf++) {
                    int col = cbl + (nf << 3);
                    if (col >= N) continue;
                    float2 bv = *(const float2*)(bias + col);
                    int row = r0 + (mt << 4);
                    *(float2*)(F1 + (size_t)row * ldc + col) =
                        make_float2(acc[mt][nf][0] + bv.x, acc[mt][nf][1] + bv.y);
                    *(float2*)(F1 + (size_t)(row + 8) * ldc + col) =
                        make_float2(acc[mt][nf][2] + bv.x, acc[mt][nf][3] + bv.y);
                }
            }
            // BN stats
            #pragma unroll
            for (int nf = 0; nf < 8; nf++) {
                int col = cbl + (nf << 3);
                bool ok = col < N;
                float2 bv = ok ? *(const float2*)(bias + col) : make_float2(0.f, 0.f);
                float s0 = 0.f, q0 = 0.f, s1 = 0.f, q1 = 0.f;
                #pragma unroll
                for (int mt = 0; mt < 2; mt++) {
                    float v0 = acc[mt][nf][0] + bv.x, v1 = acc[mt][nf][1] + bv.y;
                    float v2 = acc[mt][nf][2] + bv.x, v3 = acc[mt][nf][3] + bv.y;
                    s0 += v0 + v2; q0 += v0 * v0 + v2 * v2;
                    s1 += v1 + v3; q1 += v1 * v1 + v3 * v3;
                }
                #pragma unroll
                for (int o = 4; o < 32; o <<= 1) {
                    s0 += __shfl_xor_sync(0xFFFFFFFFu, s0, o);
                    q0 += __shfl_xor_sync(0xFFFFFFFFu, q0, o);
                    s1 += __shfl_xor_sync(0xFFFFFFFFu, s1, o);
                    q1 += __shfl_xor_sync(0xFFFFFFFFu, q1, o);
                }
                if (lane < 4 && ok) {
                    atomicAdd(&g_stats[col], s0);
                    atomicAdd(&g_stats[col + 1], s1);
                    atomicAdd(&g_stats[HH + col], q0);
                    atomicAdd(&g_stats[HH + col + 1], q1);
                }
            }
        } else {
            #pragma unroll
            for (int mt = 0; mt < 2; mt++) {
                #pragma unroll
                for (int nf = 0; nf < 8; nf++) {
                    int col = cbl + (nf << 3);
                    if (col >= N) continue;
                    float2 bv = *(const float2*)(bias + col);
                    int row = r0 + (mt << 4);
                    float v0 = fmaxf(acc[mt][nf][0] + bv.x, 0.f);
                    float v1 = fmaxf(acc[mt][nf][1] + bv.y, 0.f);
                    float v2 = fmaxf(acc[mt][nf][2] + bv.x, 0.f);
                    float v3 = fmaxf(acc[mt][nf][3] + bv.y, 0.f);
                    float2 o0 = *(const float2*)(F2 + (size_t)row * ldc + col);
                    float2 o1 = *(const float2*)(F2 + (size_t)(row + 8) * ldc + col);
                    *(float2*)(F2 + (size_t)row * ldc + col) =
                        make_float2(o0.x + v0, o0.y + v1);
                    *(float2*)(F2 + (size_t)(row + 8) * ldc + col) =
                        make_float2(o1.x + v2, o1.y + v3);
                }
            }
        }
    } else {
        // CFG 2: predictor — relu then per-row dot with Wp2 (=bias2), atomic out (=F2)
        float s[4] = {0.f, 0.f, 0.f, 0.f};
        #pragma unroll
        for (int mt = 0; mt < 2; mt++) {
            #pragma unroll
            for (int nf = 0; nf < 8; nf++) {
                int col = cbl + (nf << 3);
                if (col < N) {
                    float2 bv = *(const float2*)(bias + col);
                    float w0 = bias2[col], w1 = bias2[col + 1];
                    float v0 = fmaxf(acc[mt][nf][0] + bv.x, 0.f);
                    float v1 = fmaxf(acc[mt][nf][1] + bv.y, 0.f);
                    float v2 = fmaxf(acc[mt][nf][2] + bv.x, 0.f);
                    float v3 = fmaxf(acc[mt][nf][3] + bv.y, 0.f);
                    s[2 * mt] += v0 * w0 + v1 * w1;
                    s[2 * mt + 1] += v2 * w0 + v3 * w1;
                }
            }
        }
        #pragma unroll
        for (int q = 0; q < 4; q++) {
            s[q] += __shfl_xor_sync(0xFFFFFFFFu, s[q], 1);
            s[q] += __shfl_xor_sync(0xFFFFFFFFu, s[q], 2);
        }
        if ((lane & 3) == 0) {
            atomicAdd(&F2[r0], s[0]);
            atomicAdd(&F2[r0 + 8], s[1]);
            atomicAdd(&F2[r0 + 16], s[2]);
            atomicAdd(&F2[r0 + 24], s[3]);
        }
    }
}

// ------------------------- BN apply -----------------------------------------
__global__ void k_bnapply(const float* __restrict__ scale, const float* __restrict__ bias,
                          int dorelu) {
    int j = threadIdx.x;
    if (j >= HH) return;
    const float invN = 1.f / (float)NN;
    float m = g_stats[j] * invN;
    float var = g_stats[HH + j] * invN - m * m;
    float co = rsqrtf(var + 1e-5f) * scale[j];
    float bi = bias[j];
    #pragma unroll
    for (int r = 0; r < 4; r++) {
        size_t o = (size_t)(blockIdx.x * 4 + r) * HH + j;
        float z = (g_z2[o] - m) * co + bi;
        if (dorelu) z = fmaxf(z, 0.f);
        g_h[o] += z;
    }
}

// h_rep split bf16 = [pooled_h | id_pool(analytic) | morgan | maccs | 0pad]
__global__ void k_assemble(const float* __restrict__ morgan, const float* __restrict__ maccs) {
    GSTRIDE(idx, GG * KPP) {
        int g = idx / KPP, c = idx % KPP;
        int cnt = g_gcnt[g];
        float denom = fmaxf((float)cnt, 1.f);
        float v;
        if (c < HH) {
            v = g_pool[(size_t)g * HH + c] / denom;
        } else if (c < HH + FF) {
            int f = c - HH;
            int cf = (f < cnt) ? ((cnt - 1 - f) / FF + 1) : 0;
            v = (float)cf / denom;
        } else if (c < HH + FF + 1024) {
            v = morgan[(size_t)g * 1024 + (c - HH - FF)];
        } else if (c < DGC) {
            v = maccs[(size_t)g * 167 + (c - HH - FF - 1024)];
        } else {
            v = 0.f;
        }
        __nv_bfloat16 hi, lo;
        split_bf16(v, hi, lo);
        g_hreph[idx] = hi;
        g_hrepl[idx] = lo;
    }
}

// ---------------------------------------------------------------------------
static inline int nblk(long long work, int t) { return (int)((work + t - 1) / t); }

extern "C" void kernel_launch(void* const* d_in, const int* in_sizes, int n_in,
                              void* d_out, int out_size) {
    const void* ord[21];
    int p = 0;
    const int* edge = nullptr;
    const int* batch = nullptr;
    for (int i = 0; i < n_in; i++) {
        if (in_sizes[i] == 2 * EE) edge = (const int*)d_in[i];
        else if (in_sizes[i] == NN) batch = (const int*)d_in[i];
        else if (p < 21) ord[p++] = d_in[i];
    }
    const float* x        = (const float*)ord[0];
    const float* morgan   = (const float*)ord[1];
    const float* maccs    = (const float*)ord[2];
    const float* W_emb    = (const float*)ord[3];
    const float* b_emb    = (const float*)ord[4];
    const float* gin_W1   = (const float*)ord[5];
    const float* gin_b1   = (const float*)ord[6];
    const float* gin_W2   = (const float*)ord[7];
    const float* gin_b2   = (const float*)ord[8];
    const float* bn_scale = (const float*)ord[9];
    const float* bn_bias  = (const float*)ord[10];
    const float* eps      = (const float*)ord[11];
    const float* vn0      = (const float*)ord[12];
    const float* vn_W1    = (const float*)ord[13];
    const float* vn_b1    = (const float*)ord[14];
    const float* vn_W2    = (const float*)ord[15];
    const float* vn_b2    = (const float*)ord[16];
    const float* Wp1      = (const float*)ord[17];
    const float* bp1      = (const float*)ord[18];
    const float* Wp2      = (const float*)ord[19];
    const float* bp2      = (const float*)ord[20];
    const int* src = edge;
    const int* dst = edge + EE;
    float* out = (float*)d_out;

    float *pz2, *pvn;
    __nv_bfloat16 *pzinh, *pzinl, *pt1h, *pt1l, *pvth, *pvtl, *pvhh, *pvhl, *phrh, *phrl;
    __nv_bfloat16 *pgW1h, *pgW1l, *pgW2h, *pgW2l, *pvW1h, *pvW1l, *pvW2h, *pvW2l, *pWph, *pWpl;
    cudaGetSymbolAddress((void**)&pz2, g_z2);
    cudaGetSymbolAddress((void**)&pvn, g_vn);
    cudaGetSymbolAddress((void**)&pzinh, g_zinh);
    cudaGetSymbolAddress((void**)&pzinl, g_zinl);
    cudaGetSymbolAddress((void**)&pt1h, g_t1h);
    cudaGetSymbolAddress((void**)&pt1l, g_t1l);
    cudaGetSymbolAddress((void**)&pvth, g_vth);
    cudaGetSymbolAddress((void**)&pvtl, g_vtl);
    cudaGetSymbolAddress((void**)&pvhh, g_vhh);
    cudaGetSymbolAddress((void**)&pvhl, g_vhl);
    cudaGetSymbolAddress((void**)&phrh, g_hreph);
    cudaGetSymbolAddress((void**)&phrl, g_hrepl);
    cudaGetSymbolAddress((void**)&pgW1h, g_gW1h);
    cudaGetSymbolAddress((void**)&pgW1l, g_gW1l);
    cudaGetSymbolAddress((void**)&pgW2h, g_gW2h);
    cudaGetSymbolAddress((void**)&pgW2l, g_gW2l);
    cudaGetSymbolAddress((void**)&pvW1h, g_vW1h);
    cudaGetSymbolAddress((void**)&pvW1l, g_vW1l);
    cudaGetSymbolAddress((void**)&pvW2h, g_vW2h);
    cudaGetSymbolAddress((void**)&pvW2l, g_vW2l);
    cudaGetSymbolAddress((void**)&pWph, g_Wph);
    cudaGetSymbolAddress((void**)&pWpl, g_Wpl);

    cudaFuncSetAttribute(k_mma<0>, cudaFuncAttributeMaxDynamicSharedMemorySize, SMEMSZ);
    cudaFuncSetAttribute(k_mma<1>, cudaFuncAttributeMaxDynamicSharedMemorySize, SMEMSZ);
    cudaFuncSetAttribute(k_mma<2>, cudaFuncAttributeMaxDynamicSharedMemorySize, SMEMSZ);

    const int T = 256;

    // setup
    k_embed<<<NN / 4, 320>>>(x, W_emb, b_emb);
    k_initvn<<<nblk(GG * HH, T), T>>>(vn0);
    k_initout<<<nblk(GG, T), T>>>(bp2, out);
    k_splitw_all<<<dim3(512, 19), T>>>(gin_W1, gin_W2, vn_W1, vn_W2, Wp1);
    k_zero_setup<<<nblk(NN + GG, T), T>>>();
    k_hist<<<nblk(EE, T), T>>>(dst, batch);
    k_scan_off<<<1, 1024>>>();
    k_scan_g<<<1, 1024>>>();
    k_scatter<<<nblk(EE, T), T>>>(src, dst);
    k_zero_pads<<<nblk(NN + GG, T), T>>>();

    for (int l = 0; l < LL; l++) {
        bool vnl = l < LL - 1;
        k_gather<<<NN / 8, 256>>>(batch, eps, l);
        if (vnl) k_vtgather<<<GG / 8, 256>>>();

        int gy = 512 + (vnl ? 16 : 0);
        k_mma<0><<<dim3(5, gy), 256, SMEMSZ>>>(
            pzinh, pzinl,
            pgW1h + (size_t)l * H2 * KP1, pgW1l + (size_t)l * H2 * KP1,
            gin_b1 + (size_t)l * H2, nullptr, pt1h, pt1l,
            pvth, pvtl,
            vnl ? pvW1h + (size_t)l * H2 * KP1 : nullptr,
            vnl ? pvW1l + (size_t)l * H2 * KP1 : nullptr,
            vnl ? vn_b1 + (size_t)l * H2 : nullptr, nullptr, pvhh, pvhl,
            512, KP1, H2, KP2);
        k_mma<1><<<dim3(3, gy), 256, SMEMSZ>>>(
            pt1h, pt1l,
            pgW2h + (size_t)l * HH * KP2, pgW2l + (size_t)l * HH * KP2,
            gin_b2 + (size_t)l * HH, pz2, nullptr, nullptr,
            pvhh, pvhl,
            vnl ? pvW2h + (size_t)l * HH * KP2 : nullptr,
            vnl ? pvW2l + (size_t)l * HH * KP2 : nullptr,
            vnl ? vn_b2 + (size_t)l * HH : nullptr, pvn, nullptr, nullptr,
            512, KP2, HH, HH);

        k_bnapply<<<NN / 4, 320>>>(bn_scale + (size_t)l * HH,
                                   bn_bias + (size_t)l * HH, vnl ? 1 : 0);
    }

    k_poolgather<<<GG / 8, 256>>>();
    k_assemble<<<nblk(GG * KPP, T), T>>>(morgan, maccs);
    k_mma<2><<<dim3(5, 16), 256, SMEMSZ>>>(
        phrh, phrl, pWph, pWpl, bp1, nullptr, nullptr, nullptr,
        nullptr, nullptr, nullptr, nullptr, Wp2, out, nullptr, nullptr,
        16, KPP, H2, H2);
}